// round 1
// baseline (speedup 1.0000x reference)
#include <cuda_runtime.h>
#include <cuda_bf16.h>
#include <math.h>

// ---------------------------------------------------------------------------
// Problem constants (from reference): B=2, S=1024, D=1024, F=4096, P=256,
// R=64, K=32.  BS = B*S = 2048.  KR = TOP_K * R = 2048.
// ---------------------------------------------------------------------------
#define DIM_D 1024
#define DIM_F 4096
#define DIM_P 256
#define DIM_R 64
#define TOPK  32
#define BS    2048
#define KR    (TOPK * DIM_R)   // 2048

// ---------------------------------------------------------------------------
// Device scratch (no cudaMalloc allowed).
// ---------------------------------------------------------------------------
__device__ int   g_idx[2][TOPK];
__device__ float g_wgt[2][TOPK];

__device__ float g_Ab1[(size_t)DIM_D * KR];       //  8 MB  (D, KR) scaled gather of fc1_A
__device__ float g_Bb1[(size_t)KR * DIM_F];       // 32 MB  (KR, F) gather of fc1_B
__device__ float g_Ab2[(size_t)DIM_F * KR];       // 32 MB  (F, KR) scaled gather of fc2_A
__device__ float g_Bb2[(size_t)KR * DIM_D];       //  8 MB  (KR, D) gather of fc2_B
__device__ float g_W1[(size_t)DIM_D * DIM_F];     // 16 MB  (D, F)
__device__ float g_W2[(size_t)DIM_F * DIM_D];     // 16 MB  (F, D)
__device__ float g_h[(size_t)BS * DIM_F];         // 32 MB  (BS, F)

// ---------------------------------------------------------------------------
// Top-K + softmax.  One block per FC (blockIdx.x = 0 -> fc1, 1 -> fc2).
// P=256 threads; 32 serial argmax rounds with a parallel smem reduction.
// ---------------------------------------------------------------------------
__global__ void topk_softmax_kernel(const float* __restrict__ logits1,
                                    const float* __restrict__ logits2) {
    const float* logits = (blockIdx.x == 0) ? logits1 : logits2;
    int which = blockIdx.x;

    __shared__ float v[DIM_P];
    __shared__ float rv[DIM_P];
    __shared__ int   ri[DIM_P];
    __shared__ float vals[TOPK];

    int t = threadIdx.x;
    v[t] = logits[t];
    __syncthreads();

    for (int k = 0; k < TOPK; k++) {
        rv[t] = v[t];
        ri[t] = t;
        __syncthreads();
        #pragma unroll
        for (int s = DIM_P / 2; s > 0; s >>= 1) {
            if (t < s) {
                // strict '>' keeps the lower index on exact ties (matches lax.top_k)
                if (rv[t + s] > rv[t]) { rv[t] = rv[t + s]; ri[t] = ri[t + s]; }
            }
            __syncthreads();
        }
        if (t == 0) {
            g_idx[which][k] = ri[0];
            vals[k] = rv[0];
            v[ri[0]] = -3.402823466e38f;
        }
        __syncthreads();
    }

    if (t == 0) {
        float mx = -3.402823466e38f;
        #pragma unroll
        for (int k = 0; k < TOPK; k++) mx = fmaxf(mx, vals[k]);
        float e[TOPK];
        float sum = 0.f;
        #pragma unroll
        for (int k = 0; k < TOPK; k++) { e[k] = expf(vals[k] - mx); sum += e[k]; }
        float inv = 1.f / sum;
        #pragma unroll
        for (int k = 0; k < TOPK; k++) g_wgt[which][k] = e[k] * inv;
    }
}

// ---------------------------------------------------------------------------
// Gather + scale A:  out (d_in, KR), out[d][k*R+r] = w[k] * A[idx[k]][d][r]
// A layout (P, d_in, R) row-major.  Vectorized float4 (R=64 multiple of 4).
// ---------------------------------------------------------------------------
__global__ void gather_A_kernel(const float* __restrict__ A, float* __restrict__ out,
                                int d_in, int which) {
    size_t total4 = (size_t)d_in * KR / 4;
    size_t vidx = (size_t)blockIdx.x * blockDim.x + threadIdx.x;
    if (vidx >= total4) return;
    size_t i = vidx * 4;
    int d = (int)(i >> 11);          // / 2048
    int c = (int)(i & 2047);
    int k = c >> 6;                   // / 64
    int r = c & 63;
    int p = g_idx[which][k];
    float w = g_wgt[which][k];
    const float4 src = *reinterpret_cast<const float4*>(
        A + (size_t)p * d_in * DIM_R + (size_t)d * DIM_R + r);
    float4 o;
    o.x = w * src.x; o.y = w * src.y; o.z = w * src.z; o.w = w * src.w;
    reinterpret_cast<float4*>(out)[vidx] = o;
}

// ---------------------------------------------------------------------------
// Gather B:  out (KR, d_out), rows [k*R : (k+1)*R) = B[idx[k]] (R, d_out).
// Contiguous per-expert copy, float4 vectorized.
// ---------------------------------------------------------------------------
__global__ void gather_B_kernel(const float* __restrict__ B, float* __restrict__ out,
                                int d_out, int which) {
    size_t total4 = (size_t)KR * d_out / 4;
    size_t vidx = (size_t)blockIdx.x * blockDim.x + threadIdx.x;
    if (vidx >= total4) return;
    size_t i = vidx * 4;
    size_t per_expert = (size_t)DIM_R * d_out;
    int k = (int)(i / per_expert);
    size_t off = i - (size_t)k * per_expert;
    int p = g_idx[which][k];
    reinterpret_cast<float4*>(out)[vidx] =
        *reinterpret_cast<const float4*>(B + (size_t)p * per_expert + off);
}

// ---------------------------------------------------------------------------
// GELU (tanh approximation, matches jax.nn.gelu approximate=True)
// ---------------------------------------------------------------------------
__device__ __forceinline__ float gelu_tanh(float x) {
    const float c0 = 0.7978845608028654f;   // sqrt(2/pi)
    const float c1 = 0.044715f;
    float x3 = x * x * x;
    return 0.5f * x * (1.0f + tanhf(c0 * (x + c1 * x3)));
}

// ---------------------------------------------------------------------------
// Tiled SGEMM: C(M,N) = A(M,K) @ B(K,N), all row-major fp32.
// 64x64 block tile, K-tile 16, 256 threads, 4x4 per thread, float4 I/O.
// Requires: M,N % 64 == 0, K % 16 == 0 (true for all 4 calls).
// ---------------------------------------------------------------------------
template <bool GELU>
__global__ void __launch_bounds__(256)
sgemm_kernel(const float* __restrict__ A, const float* __restrict__ B,
             float* __restrict__ C, int M, int N, int K) {
    __shared__ float As[16][64];   // transposed A tile: As[k][m]
    __shared__ float Bs[16][64];   // Bs[k][n]

    int t  = threadIdx.x;          // 0..255
    int tx = t & 15;               // 0..15 -> 4 output cols each
    int ty = t >> 4;               // 0..15 -> 4 output rows each
    int rowBase = blockIdx.y * 64;
    int colBase = blockIdx.x * 64;

    // loader indices
    int aRow  = t >> 2;            // 0..63
    int aCol4 = (t & 3) * 4;       // 0,4,8,12
    int bRow  = t >> 4;            // 0..15
    int bCol4 = (t & 15) * 4;      // 0..60

    float acc[4][4] = {};

    const float* Aptr = A + (size_t)(rowBase + aRow) * K + aCol4;
    const float* Bptr = B + (size_t)bRow * N + colBase + bCol4;

    for (int k0 = 0; k0 < K; k0 += 16) {
        float4 av = *reinterpret_cast<const float4*>(Aptr + k0);
        As[aCol4 + 0][aRow] = av.x;
        As[aCol4 + 1][aRow] = av.y;
        As[aCol4 + 2][aRow] = av.z;
        As[aCol4 + 3][aRow] = av.w;
        float4 bv = *reinterpret_cast<const float4*>(Bptr + (size_t)k0 * N);
        *reinterpret_cast<float4*>(&Bs[bRow][bCol4]) = bv;
        __syncthreads();

        #pragma unroll
        for (int kk = 0; kk < 16; kk++) {
            float4 a4 = *reinterpret_cast<const float4*>(&As[kk][ty * 4]);
            float4 b4 = *reinterpret_cast<const float4*>(&Bs[kk][tx * 4]);
            float av_[4] = {a4.x, a4.y, a4.z, a4.w};
            float bv_[4] = {b4.x, b4.y, b4.z, b4.w};
            #pragma unroll
            for (int i = 0; i < 4; i++)
                #pragma unroll
                for (int j = 0; j < 4; j++)
                    acc[i][j] = fmaf(av_[i], bv_[j], acc[i][j]);
        }
        __syncthreads();
    }

    #pragma unroll
    for (int i = 0; i < 4; i++) {
        int row = rowBase + ty * 4 + i;
        float v0 = acc[i][0], v1 = acc[i][1], v2 = acc[i][2], v3 = acc[i][3];
        if (GELU) {
            v0 = gelu_tanh(v0); v1 = gelu_tanh(v1);
            v2 = gelu_tanh(v2); v3 = gelu_tanh(v3);
        }
        float4 o = make_float4(v0, v1, v2, v3);
        *reinterpret_cast<float4*>(&C[(size_t)row * N + colBase + tx * 4]) = o;
    }
}

// ---------------------------------------------------------------------------
// Launch
// ---------------------------------------------------------------------------
extern "C" void kernel_launch(void* const* d_in, const int* in_sizes, int n_in,
                              void* d_out, int out_size) {
    const float* x      = (const float*)d_in[0];   // (2,1024,1024) -> (2048,1024)
    const float* fc1_A  = (const float*)d_in[1];   // (256,1024,64)
    const float* fc1_B  = (const float*)d_in[2];   // (256,64,4096)
    const float* fc2_A  = (const float*)d_in[3];   // (256,4096,64)
    const float* fc2_B  = (const float*)d_in[4];   // (256,64,1024)
    const float* l1     = (const float*)d_in[5];   // (256,)
    const float* l2     = (const float*)d_in[6];   // (256,)
    float* out = (float*)d_out;                    // (2048,1024)

    float *Ab1, *Bb1, *Ab2, *Bb2, *W1, *W2, *h;
    cudaGetSymbolAddress((void**)&Ab1, g_Ab1);
    cudaGetSymbolAddress((void**)&Bb1, g_Bb1);
    cudaGetSymbolAddress((void**)&Ab2, g_Ab2);
    cudaGetSymbolAddress((void**)&Bb2, g_Bb2);
    cudaGetSymbolAddress((void**)&W1,  g_W1);
    cudaGetSymbolAddress((void**)&W2,  g_W2);
    cudaGetSymbolAddress((void**)&h,   g_h);

    // 1. top-k + softmax for both FCs
    topk_softmax_kernel<<<2, 256>>>(l1, l2);

    // 2. gathers (scaled A-gather, plain B-gather)
    {
        size_t n4;
        n4 = (size_t)DIM_D * KR / 4;
        gather_A_kernel<<<(unsigned)((n4 + 255) / 256), 256>>>(fc1_A, Ab1, DIM_D, 0);
        n4 = (size_t)KR * DIM_F / 4;
        gather_B_kernel<<<(unsigned)((n4 + 255) / 256), 256>>>(fc1_B, Bb1, DIM_F, 0);
        n4 = (size_t)DIM_F * KR / 4;
        gather_A_kernel<<<(unsigned)((n4 + 255) / 256), 256>>>(fc2_A, Ab2, DIM_F, 1);
        n4 = (size_t)KR * DIM_D / 4;
        gather_B_kernel<<<(unsigned)((n4 + 255) / 256), 256>>>(fc2_B, Bb2, DIM_D, 1);
    }

    // 3. compose W1 = Ab1 (1024,2048) @ Bb1 (2048,4096)
    {
        dim3 grid(DIM_F / 64, DIM_D / 64);
        sgemm_kernel<false><<<grid, 256>>>(Ab1, Bb1, W1, DIM_D, DIM_F, KR);
    }
    // 4. compose W2 = Ab2 (4096,2048) @ Bb2 (2048,1024)
    {
        dim3 grid(DIM_D / 64, DIM_F / 64);
        sgemm_kernel<false><<<grid, 256>>>(Ab2, Bb2, W2, DIM_F, DIM_D, KR);
    }
    // 5. h = gelu(x (2048,1024) @ W1 (1024,4096))
    {
        dim3 grid(DIM_F / 64, BS / 64);
        sgemm_kernel<true><<<grid, 256>>>(x, W1, h, BS, DIM_F, DIM_D);
    }
    // 6. out = h (2048,4096) @ W2 (4096,1024)
    {
        dim3 grid(DIM_D / 64, BS / 64);
        sgemm_kernel<false><<<grid, 256>>>(h, W2, out, BS, DIM_D, DIM_F);
    }
}

// round 3
// speedup vs baseline: 5.2354x; 5.2354x over previous
#include <cuda_runtime.h>
#include <cuda_bf16.h>
#include <math.h>
#include <stdint.h>

// ---------------------------------------------------------------------------
// Problem constants: B=2, S=1024, D=1024, F=4096, P=256, R=64, K=32.
// ---------------------------------------------------------------------------
#define DIM_D 1024
#define DIM_F 4096
#define DIM_P 256
#define DIM_R 64
#define TOPK  32
#define BS    2048
#define KR    (TOPK * DIM_R)   // 2048

// ---------------------------------------------------------------------------
// Feature detection: tcgen05 only exists on the sm_103a ("ALL") target.
// The harness also emits a plain compute_103 PTX pass; there the guard
// selects an FFMA fallback with identical semantics so EITHER cubin is correct.
// ---------------------------------------------------------------------------
#if defined(__CUDA_ARCH__)
#  ifdef __CUDA_ARCH_HAS_FEATURE__
#    if __CUDA_ARCH_HAS_FEATURE__(SM103_ALL)
#      define TC_PATH 1
#    endif
#  endif
#  ifndef TC_PATH
#    ifdef __CUDA_ARCH_FEAT_SM103_ALL
#      define TC_PATH 1
#    else
#      define TC_PATH 0
#    endif
#  endif
#else
#  define TC_PATH 0
#endif

// ---------------------------------------------------------------------------
// PTX helpers
// ---------------------------------------------------------------------------
__device__ __forceinline__ uint32_t smem_to_u32(const void* smem_ptr) {
    uint32_t addr;
    asm("{ .reg .u64 tmp; cvta.to.shared.u64 tmp, %1; cvt.u32.u64 %0, tmp; }"
        : "=r"(addr) : "l"(smem_ptr));
    return addr;
}
#define SMEM_SWIZZLE_128B(byte_offset) \
    ((byte_offset) ^ (((byte_offset) >> 3) & 0x70))

#if TC_PATH
__device__ __forceinline__ uint32_t elect_one_pred() {
    uint32_t pred;
    asm volatile(
        "{\n\t.reg .pred p;\n\telect.sync _|p, 0xFFFFFFFF;\n\tselp.b32 %0, 1, 0, p;\n\t}"
        : "=r"(pred));
    return pred;
}

static constexpr uint64_t SMEM_DESC_BASE_SW128 =
    (uint64_t(2)  << 61) | (uint64_t(1) << 46) | (uint64_t(64) << 32) | (uint64_t(1) << 16);
#define MAKE_SMEM_DESC(base_addr) \
    (SMEM_DESC_BASE_SW128 | ((uint64_t)((base_addr) >> 4) & 0x3FFF))

#define TCGEN05_ALLOC(smem_result_addr, nCols) \
    asm volatile("tcgen05.alloc.cta_group::1.sync.aligned.shared::cta.b32 [%0], %1;" \
        :: "r"((uint32_t)(smem_result_addr)), "r"((uint32_t)(nCols)) : "memory")
#define TCGEN05_DEALLOC(tmem_addr, nCols) \
    asm volatile("tcgen05.dealloc.cta_group::1.sync.aligned.b32 %0, %1;" \
        :: "r"(tmem_addr), "r"((uint32_t)(nCols)))
#define TCGEN05_RELINQUISH_ALLOC_PERMIT() \
    asm volatile("tcgen05.relinquish_alloc_permit.cta_group::1.sync.aligned;")
#define TCGEN05_COMMIT(mbar_smem_addr) \
    asm volatile("tcgen05.commit.cta_group::1.mbarrier::arrive::one.shared::cluster.b64 [%0];" \
        :: "r"((uint32_t)(mbar_smem_addr)) : "memory")
#define TCGEN05_FENCE_AFTER() \
    asm volatile("tcgen05.fence::after_thread_sync;" ::: "memory")
#define TCGEN05_FENCE_BEFORE() \
    asm volatile("tcgen05.fence::before_thread_sync;" ::: "memory")
#define TCGEN05_WAIT_LD() \
    asm volatile("tcgen05.wait::ld.sync.aligned;" ::: "memory")
#define FENCE_PROXY_ASYNC_SHARED_CTA() \
    asm volatile("fence.proxy.async.shared::cta;" ::: "memory")
#define MBARRIER_INIT(mbar_smem_addr, count) \
    asm volatile("mbarrier.init.shared.b64 [%0], %1;" \
        :: "r"((uint32_t)(mbar_smem_addr)), "r"((uint32_t)(count)) : "memory")
#define MBARRIER_WAIT_PARITY(mbar_smem_addr, phase_parity) do { \
    uint32_t _mbar = (uint32_t)(mbar_smem_addr); \
    uint32_t _parity = (uint32_t)(phase_parity); \
    uint32_t _done; \
    asm volatile( \
        "{\n\t.reg .pred p;\n\t" \
        "mbarrier.try_wait.parity.acquire.cta.shared::cta.b64 p, [%1], %2;\n\t" \
        "selp.b32 %0, 1, 0, p;\n\t}" \
        : "=r"(_done) : "r"(_mbar), "r"(_parity) : "memory"); \
    if (!_done) { \
        asm volatile( \
            "{\n\t.reg .pred P1;\n\t" \
            "WAIT_LOOP_%=:\n\t" \
            "mbarrier.try_wait.parity.acquire.cta.shared::cta.b64 P1, [%0], %1, 0x989680;\n\t" \
            "@P1 bra.uni WAIT_DONE_%=;\n\t" \
            "bra.uni WAIT_LOOP_%=;\n\t" \
            "WAIT_DONE_%=:\n\t}" \
            :: "r"(_mbar), "r"(_parity) : "memory"); \
    } \
} while(0)

#define TCGEN05_LD_32X32B_X32(r, tmem_addr) \
    asm volatile( \
        "tcgen05.ld.sync.aligned.32x32b.x32.b32 " \
        "{%0, %1, %2, %3, %4, %5, %6, %7, " \
        " %8, %9, %10, %11, %12, %13, %14, %15, " \
        " %16, %17, %18, %19, %20, %21, %22, %23, " \
        " %24, %25, %26, %27, %28, %29, %30, %31}, [%32];" \
        : "=r"((r)[0]),  "=r"((r)[1]),  "=r"((r)[2]),  "=r"((r)[3]), \
          "=r"((r)[4]),  "=r"((r)[5]),  "=r"((r)[6]),  "=r"((r)[7]), \
          "=r"((r)[8]),  "=r"((r)[9]),  "=r"((r)[10]), "=r"((r)[11]), \
          "=r"((r)[12]), "=r"((r)[13]), "=r"((r)[14]), "=r"((r)[15]), \
          "=r"((r)[16]), "=r"((r)[17]), "=r"((r)[18]), "=r"((r)[19]), \
          "=r"((r)[20]), "=r"((r)[21]), "=r"((r)[22]), "=r"((r)[23]), \
          "=r"((r)[24]), "=r"((r)[25]), "=r"((r)[26]), "=r"((r)[27]), \
          "=r"((r)[28]), "=r"((r)[29]), "=r"((r)[30]), "=r"((r)[31]) \
        : "r"(tmem_addr))

// SS-mode cg1 kind::f16 MMA (bf16 in, f32 accum), M=128, N=128.
__device__ __forceinline__ void mma_f16_ss(uint32_t d_tmem, uint64_t a_desc,
                                           uint64_t b_desc, uint32_t idesc, bool en) {
    uint32_t e = en ? 1u : 0u;
    asm volatile(
        "{\n\t.reg .pred p;\n\tsetp.ne.u32 p, %4, 0;\n\t"
        "tcgen05.mma.cta_group::1.kind::f16 [%0], %1, %2, %3, {%5, %5, %5, %5}, p;\n\t}"
        :: "r"(d_tmem), "l"(a_desc), "l"(b_desc), "r"(idesc), "r"(e), "r"(0u)
        : "memory");
}

// idesc: dtype=F32 (bit4), atype=BF16 (bit7), btype=BF16 (bit10),
// N/8 @ [17:22], M/16 @ [24:28].  (Validated against example 0x8080490.)
static constexpr uint32_t IDESC_128x128 =
    (1u << 4) | (1u << 7) | (1u << 10) | ((128u / 8u) << 17) | ((128u / 16u) << 24);
#endif  // TC_PATH

// ---------------------------------------------------------------------------
// Device scratch (bf16 hi/lo split buffers)
// ---------------------------------------------------------------------------
__device__ int   g_idx[2][TOPK];
__device__ float g_wgt[2][TOPK];

__device__ __nv_bfloat16 g_xh[(size_t)BS * DIM_D];
__device__ __nv_bfloat16 g_xl[(size_t)BS * DIM_D];
__device__ __nv_bfloat16 g_Ab1h[(size_t)DIM_D * KR];
__device__ __nv_bfloat16 g_Ab1l[(size_t)DIM_D * KR];
__device__ __nv_bfloat16 g_Bb1th[(size_t)DIM_F * KR];
__device__ __nv_bfloat16 g_Bb1tl[(size_t)DIM_F * KR];
__device__ __nv_bfloat16 g_Ab2h[(size_t)DIM_F * KR];
__device__ __nv_bfloat16 g_Ab2l[(size_t)DIM_F * KR];
__device__ __nv_bfloat16 g_Bb2th[(size_t)DIM_D * KR];
__device__ __nv_bfloat16 g_Bb2tl[(size_t)DIM_D * KR];
__device__ __nv_bfloat16 g_W1th[(size_t)DIM_F * DIM_D];
__device__ __nv_bfloat16 g_W1tl[(size_t)DIM_F * DIM_D];
__device__ __nv_bfloat16 g_W2th[(size_t)DIM_D * DIM_F];
__device__ __nv_bfloat16 g_W2tl[(size_t)DIM_D * DIM_F];
__device__ __nv_bfloat16 g_hh[(size_t)BS * DIM_F];
__device__ __nv_bfloat16 g_hl[(size_t)BS * DIM_F];

__device__ __forceinline__ void split_bf16(float v, __nv_bfloat16& h, __nv_bfloat16& l) {
    h = __float2bfloat16(v);
    l = __float2bfloat16(v - __bfloat162float(h));
}

// ---------------------------------------------------------------------------
// Top-K + softmax (one block per FC)
// ---------------------------------------------------------------------------
__global__ void topk_softmax_kernel(const float* __restrict__ logits1,
                                    const float* __restrict__ logits2) {
    const float* logits = (blockIdx.x == 0) ? logits1 : logits2;
    int which = blockIdx.x;
    __shared__ float v[DIM_P];
    __shared__ float rv[DIM_P];
    __shared__ int   ri[DIM_P];
    __shared__ float vals[TOPK];
    int t = threadIdx.x;
    v[t] = logits[t];
    __syncthreads();
    for (int k = 0; k < TOPK; k++) {
        rv[t] = v[t]; ri[t] = t;
        __syncthreads();
        #pragma unroll
        for (int s = DIM_P / 2; s > 0; s >>= 1) {
            if (t < s) {
                if (rv[t + s] > rv[t]) { rv[t] = rv[t + s]; ri[t] = ri[t + s]; }
            }
            __syncthreads();
        }
        if (t == 0) {
            g_idx[which][k] = ri[0];
            vals[k] = rv[0];
            v[ri[0]] = -3.402823466e38f;
        }
        __syncthreads();
    }
    if (t == 0) {
        float mx = -3.402823466e38f;
        #pragma unroll
        for (int k = 0; k < TOPK; k++) mx = fmaxf(mx, vals[k]);
        float e[TOPK]; float sum = 0.f;
        #pragma unroll
        for (int k = 0; k < TOPK; k++) { e[k] = expf(vals[k] - mx); sum += e[k]; }
        float inv = 1.f / sum;
        #pragma unroll
        for (int k = 0; k < TOPK; k++) g_wgt[which][k] = e[k] * inv;
    }
}

// ---------------------------------------------------------------------------
// Scaled A gather -> bf16 hi/lo: out (d_in, KR), out[d][k*64+r] = w_k*A[p_k][d][r]
// ---------------------------------------------------------------------------
__global__ void gather_A_kernel(const float* __restrict__ A,
                                __nv_bfloat16* __restrict__ hi,
                                __nv_bfloat16* __restrict__ lo,
                                int d_in, int which) {
    size_t total4 = (size_t)d_in * KR / 4;
    size_t vidx = (size_t)blockIdx.x * blockDim.x + threadIdx.x;
    if (vidx >= total4) return;
    size_t i = vidx * 4;
    int d = (int)(i >> 11);
    int c = (int)(i & 2047);
    int k = c >> 6;
    int r = c & 63;
    int p = g_idx[which][k];
    float w = g_wgt[which][k];
    float4 s = *reinterpret_cast<const float4*>(A + ((size_t)p * d_in + d) * DIM_R + r);
    union { __nv_bfloat16 b[4]; uint2 u; } uh, ul;
    split_bf16(w * s.x, uh.b[0], ul.b[0]);
    split_bf16(w * s.y, uh.b[1], ul.b[1]);
    split_bf16(w * s.z, uh.b[2], ul.b[2]);
    split_bf16(w * s.w, uh.b[3], ul.b[3]);
    *reinterpret_cast<uint2*>(hi + i) = uh.u;
    *reinterpret_cast<uint2*>(lo + i) = ul.u;
}

// ---------------------------------------------------------------------------
// Transposed B gather -> bf16 hi/lo: out (d_out, KR), out[f][k*64+r] = B[p_k][r][f]
// ---------------------------------------------------------------------------
__global__ void gather_Bt_kernel(const float* __restrict__ B,
                                 __nv_bfloat16* __restrict__ hi,
                                 __nv_bfloat16* __restrict__ lo,
                                 int d_out, int which) {
    __shared__ float tile[64][65];
    int k  = blockIdx.y;
    int f0 = blockIdx.x * 64;
    int p  = g_idx[which][k];
    int tid = threadIdx.x;
    const float* src = B + (size_t)p * DIM_R * d_out + f0;
    #pragma unroll
    for (int j = 0; j < 16; j++) {
        int idx = tid + 256 * j;
        int r = idx >> 6, f = idx & 63;
        tile[r][f] = src[(size_t)r * d_out + f];
    }
    __syncthreads();
    int ow = tid >> 2, seg = tid & 3;
    union { __nv_bfloat16 b[8]; uint4 u; } uh0, uh1, ul0, ul1;
    #pragma unroll
    for (int e = 0; e < 16; e++) {
        float v = tile[seg * 16 + e][ow];
        __nv_bfloat16 h, l; split_bf16(v, h, l);
        if (e < 8) { uh0.b[e] = h; ul0.b[e] = l; }
        else       { uh1.b[e - 8] = h; ul1.b[e - 8] = l; }
    }
    size_t o = (size_t)(f0 + ow) * KR + (size_t)k * 64 + (size_t)seg * 16;
    *reinterpret_cast<uint4*>(hi + o)     = uh0.u;
    *reinterpret_cast<uint4*>(hi + o + 8) = uh1.u;
    *reinterpret_cast<uint4*>(lo + o)     = ul0.u;
    *reinterpret_cast<uint4*>(lo + o + 8) = ul1.u;
}

// ---------------------------------------------------------------------------
// Elementwise fp32 -> bf16 hi/lo split (for x)
// ---------------------------------------------------------------------------
__global__ void conv_split_kernel(const float* __restrict__ in,
                                  __nv_bfloat16* __restrict__ hi,
                                  __nv_bfloat16* __restrict__ lo,
                                  size_t total4) {
    size_t vidx = (size_t)blockIdx.x * blockDim.x + threadIdx.x;
    if (vidx >= total4) return;
    float4 s = reinterpret_cast<const float4*>(in)[vidx];
    union { __nv_bfloat16 b[4]; uint2 u; } uh, ul;
    split_bf16(s.x, uh.b[0], ul.b[0]);
    split_bf16(s.y, uh.b[1], ul.b[1]);
    split_bf16(s.z, uh.b[2], ul.b[2]);
    split_bf16(s.w, uh.b[3], ul.b[3]);
    reinterpret_cast<uint2*>(hi)[vidx] = uh.u;
    reinterpret_cast<uint2*>(lo)[vidx] = ul.u;
}

__device__ __forceinline__ float gelu_tanh(float x) {
    const float c0 = 0.7978845608028654f;
    const float c1 = 0.044715f;
    float x3 = x * x * x;
    return 0.5f * x * (1.0f + tanhf(c0 * (x + c1 * x3)));
}

// ---------------------------------------------------------------------------
// GEMM: D(M,N) = (Ahi+Alo)(M,K) @ [(Bhi+Blo)(N,K)]^T, K-major bf16 operands.
// Grid: (N/256, M/128), 256 threads.
// EPI: 0 = fp32 store, 1 = bf16 hi/lo store, 2 = gelu + bf16 hi/lo store.
// TC_PATH=1: tcgen05, 3-product bf16-split, double-buffered.
// TC_PATH=0: FFMA fallback (hi+lo reconstructed fp32), identical results shape.
// ---------------------------------------------------------------------------
#define STAGE_BYTES 98304
#define OFF_TILES   1024
#define GEMM_SMEM   (OFF_TILES + 2 * STAGE_BYTES)   // 197632

template <int EPI>
__global__ void __launch_bounds__(256, 1)
gemm_ts_kernel(const __nv_bfloat16* __restrict__ Ahi,
               const __nv_bfloat16* __restrict__ Alo,
               const __nv_bfloat16* __restrict__ Bhi,
               const __nv_bfloat16* __restrict__ Blo,
               int K, int N_total,
               float* __restrict__ outF,
               __nv_bfloat16* __restrict__ outHi,
               __nv_bfloat16* __restrict__ outLo) {
    extern __shared__ __align__(1024) char smem[];
    int tid = threadIdx.x;
    int m0 = blockIdx.y * 128;
    int n0 = blockIdx.x * 256;

#if TC_PATH
    uint32_t sb = smem_to_u32(smem);
    int wid = tid >> 5;
    int lid = tid & 31;

    if (wid == 0) TCGEN05_ALLOC(sb + 0, 256);
    if (tid == 0) { MBARRIER_INIT(sb + 8, 1); MBARRIER_INIT(sb + 16, 1); }
    __syncthreads();
    uint32_t tmem;
    asm volatile("ld.shared.b32 %0, [%1];" : "=r"(tmem) : "r"(sb + 0));

    int ph0 = 0, ph1 = 0;
    int NC = K >> 6;

    #pragma unroll 1
    for (int s = 0; s < NC; s++) {
        int st = s & 1;
        if (s >= 2) {
            if (st == 0) { MBARRIER_WAIT_PARITY(sb + 8, ph0 & 1); ph0++; }
            else         { MBARRIER_WAIT_PARITY(sb + 16, ph1 & 1); ph1++; }
        }
        int k0 = s << 6;
        char* stage = smem + OFF_TILES + st * STAGE_BYTES;
        #pragma unroll
        for (int i = 0; i < 4; i++) {
            int cid = tid + 256 * i;
            int row = cid >> 3, c16 = cid & 7;
            size_t go = ((size_t)(m0 + row) * K + k0) * 2 + c16 * 16;
            uint4 vh = *reinterpret_cast<const uint4*>((const char*)Ahi + go);
            uint4 vl = *reinterpret_cast<const uint4*>((const char*)Alo + go);
            uint32_t sw = SMEM_SWIZZLE_128B((uint32_t)(row * 128 + c16 * 16));
            *reinterpret_cast<uint4*>(stage + sw)         = vh;
            *reinterpret_cast<uint4*>(stage + 16384 + sw) = vl;
        }
        #pragma unroll
        for (int i = 0; i < 8; i++) {
            int cid = tid + 256 * i;
            int row = cid >> 3, c16 = cid & 7;
            size_t go = ((size_t)(n0 + row) * K + k0) * 2 + c16 * 16;
            uint4 vh = *reinterpret_cast<const uint4*>((const char*)Bhi + go);
            uint4 vl = *reinterpret_cast<const uint4*>((const char*)Blo + go);
            uint32_t sw = SMEM_SWIZZLE_128B((uint32_t)(row * 128 + c16 * 16));
            *reinterpret_cast<uint4*>(stage + 32768 + sw) = vh;
            *reinterpret_cast<uint4*>(stage + 65536 + sw) = vl;
        }
        FENCE_PROXY_ASYNC_SHARED_CTA();
        __syncthreads();

        if (wid == 0 && elect_one_pred()) {
            uint32_t base = sb + OFF_TILES + st * STAGE_BYTES;
            uint64_t dAh = MAKE_SMEM_DESC(base);
            uint64_t dAl = MAKE_SMEM_DESC(base + 16384);
            uint64_t dBh = MAKE_SMEM_DESC(base + 32768);
            uint64_t dBl = MAKE_SMEM_DESC(base + 65536);
            #pragma unroll
            for (int c = 0; c < 3; c++) {
                uint64_t dA = (c == 2) ? dAl : dAh;
                uint64_t dB = (c == 1) ? dBl : dBh;
                #pragma unroll
                for (int half = 0; half < 2; half++) {
                    #pragma unroll
                    for (int ks = 0; ks < 4; ks++) {
                        bool en = !(s == 0 && c == 0 && ks == 0);
                        mma_f16_ss(tmem + half * 128,
                                   dA + ks * 2,
                                   dB + (uint64_t)half * 1024 + ks * 2,
                                   IDESC_128x128, en);
                    }
                }
            }
            TCGEN05_COMMIT(sb + 8 + st * 8);
        }
    }

    MBARRIER_WAIT_PARITY(sb + 8, ph0 & 1);
    MBARRIER_WAIT_PARITY(sb + 16, ph1 & 1);
    TCGEN05_FENCE_AFTER();

    if (wid < 4) {
        int row = m0 + wid * 32 + lid;
        #pragma unroll 1
        for (int nb = 0; nb < 8; nb++) {
            uint32_t r[32];
            TCGEN05_LD_32X32B_X32(r, tmem + nb * 32);
            TCGEN05_WAIT_LD();
            int nc0 = n0 + nb * 32;
            if (EPI == 0) {
                #pragma unroll
                for (int j = 0; j < 8; j++) {
                    float4 o = make_float4(__uint_as_float(r[4 * j + 0]),
                                           __uint_as_float(r[4 * j + 1]),
                                           __uint_as_float(r[4 * j + 2]),
                                           __uint_as_float(r[4 * j + 3]));
                    *reinterpret_cast<float4*>(outF + (size_t)row * N_total + nc0 + 4 * j) = o;
                }
            } else {
                #pragma unroll
                for (int j = 0; j < 4; j++) {
                    union { __nv_bfloat16 b[8]; uint4 u; } uh, ul;
                    #pragma unroll
                    for (int e = 0; e < 8; e++) {
                        float v = __uint_as_float(r[8 * j + e]);
                        if (EPI == 2) v = gelu_tanh(v);
                        split_bf16(v, uh.b[e], ul.b[e]);
                    }
                    size_t o = (size_t)row * N_total + nc0 + 8 * j;
                    *reinterpret_cast<uint4*>(outHi + o) = uh.u;
                    *reinterpret_cast<uint4*>(outLo + o) = ul.u;
                }
            }
        }
        TCGEN05_FENCE_BEFORE();
    }

    __syncthreads();
    if (wid == 0) {
        TCGEN05_RELINQUISH_ALLOC_PERMIT();
        TCGEN05_DEALLOC(tmem, 256);
    }
#else
    // ---------------- FFMA fallback (no tcgen05 on this target) ------------
    // Process the 128x256 tile as four 128x64 chunks; 16-deep K slices in smem.
    float* As = reinterpret_cast<float*>(smem);             // [16][132]
    float* Bs = reinterpret_cast<float*>(smem) + 16 * 132;  // [16][68]

    int tx = tid & 15;   // 4 cols each
    int ty = tid >> 4;   // 8 rows each

    #pragma unroll 1
    for (int nchunk = 0; nchunk < 4; nchunk++) {
        int nbase = n0 + nchunk * 64;
        float acc[8][4];
        #pragma unroll
        for (int i = 0; i < 8; i++)
            #pragma unroll
            for (int j = 0; j < 4; j++) acc[i][j] = 0.f;

        #pragma unroll 1
        for (int k0 = 0; k0 < K; k0 += 16) {
            {   // A slice: 128 rows x 16 k
                int row = tid >> 1;
                int kseg = (tid & 1) * 8;
                size_t go = (size_t)(m0 + row) * K + k0 + kseg;
                union { uint4 u; __nv_bfloat16 b[8]; } vh, vl;
                vh.u = *reinterpret_cast<const uint4*>(Ahi + go);
                vl.u = *reinterpret_cast<const uint4*>(Alo + go);
                #pragma unroll
                for (int e = 0; e < 8; e++)
                    As[(kseg + e) * 132 + row] =
                        __bfloat162float(vh.b[e]) + __bfloat162float(vl.b[e]);
            }
            {   // B slice: 64 rows x 16 k
                int row = tid >> 2;
                int kseg = (tid & 3) * 4;
                size_t go = (size_t)(nbase + row) * K + k0 + kseg;
                union { uint2 u; __nv_bfloat16 b[4]; } vh, vl;
                vh.u = *reinterpret_cast<const uint2*>(Bhi + go);
                vl.u = *reinterpret_cast<const uint2*>(Blo + go);
                #pragma unroll
                for (int e = 0; e < 4; e++)
                    Bs[(kseg + e) * 68 + row] =
                        __bfloat162float(vh.b[e]) + __bfloat162float(vl.b[e]);
            }
            __syncthreads();
            #pragma unroll
            for (int kk = 0; kk < 16; kk++) {
                float a0[8], b0[4];
                float4 a4a = *reinterpret_cast<const float4*>(&As[kk * 132 + ty * 8]);
                float4 a4b = *reinterpret_cast<const float4*>(&As[kk * 132 + ty * 8 + 4]);
                float4 b4  = *reinterpret_cast<const float4*>(&Bs[kk * 68 + tx * 4]);
                a0[0]=a4a.x; a0[1]=a4a.y; a0[2]=a4a.z; a0[3]=a4a.w;
                a0[4]=a4b.x; a0[5]=a4b.y; a0[6]=a4b.z; a0[7]=a4b.w;
                b0[0]=b4.x;  b0[1]=b4.y;  b0[2]=b4.z;  b0[3]=b4.w;
                #pragma unroll
                for (int i = 0; i < 8; i++)
                    #pragma unroll
                    for (int j = 0; j < 4; j++)
                        acc[i][j] = fmaf(a0[i], b0[j], acc[i][j]);
            }
            __syncthreads();
        }

        #pragma unroll
        for (int i = 0; i < 8; i++) {
            int row = m0 + ty * 8 + i;
            int col = nbase + tx * 4;
            if (EPI == 0) {
                float4 o = make_float4(acc[i][0], acc[i][1], acc[i][2], acc[i][3]);
                *reinterpret_cast<float4*>(outF + (size_t)row * N_total + col) = o;
            } else {
                union { __nv_bfloat16 b[4]; uint2 u; } uh, ul;
                #pragma unroll
                for (int j = 0; j < 4; j++) {
                    float v = acc[i][j];
                    if (EPI == 2) v = gelu_tanh(v);
                    split_bf16(v, uh.b[j], ul.b[j]);
                }
                size_t o = (size_t)row * N_total + col;
                *reinterpret_cast<uint2*>(outHi + o) = uh.u;
                *reinterpret_cast<uint2*>(outLo + o) = ul.u;
            }
        }
    }
#endif
}

// ---------------------------------------------------------------------------
// Launch
// ---------------------------------------------------------------------------
extern "C" void kernel_launch(void* const* d_in, const int* in_sizes, int n_in,
                              void* d_out, int out_size) {
    const float* x     = (const float*)d_in[0];
    const float* fc1_A = (const float*)d_in[1];
    const float* fc1_B = (const float*)d_in[2];
    const float* fc2_A = (const float*)d_in[3];
    const float* fc2_B = (const float*)d_in[4];
    const float* l1    = (const float*)d_in[5];
    const float* l2    = (const float*)d_in[6];
    float* out = (float*)d_out;

    __nv_bfloat16 *xh, *xl, *Ab1h, *Ab1l, *Bb1th, *Bb1tl, *Ab2h, *Ab2l,
                  *Bb2th, *Bb2tl, *W1th, *W1tl, *W2th, *W2tl, *hh, *hl;
    cudaGetSymbolAddress((void**)&xh, g_xh);     cudaGetSymbolAddress((void**)&xl, g_xl);
    cudaGetSymbolAddress((void**)&Ab1h, g_Ab1h); cudaGetSymbolAddress((void**)&Ab1l, g_Ab1l);
    cudaGetSymbolAddress((void**)&Bb1th, g_Bb1th); cudaGetSymbolAddress((void**)&Bb1tl, g_Bb1tl);
    cudaGetSymbolAddress((void**)&Ab2h, g_Ab2h); cudaGetSymbolAddress((void**)&Ab2l, g_Ab2l);
    cudaGetSymbolAddress((void**)&Bb2th, g_Bb2th); cudaGetSymbolAddress((void**)&Bb2tl, g_Bb2tl);
    cudaGetSymbolAddress((void**)&W1th, g_W1th); cudaGetSymbolAddress((void**)&W1tl, g_W1tl);
    cudaGetSymbolAddress((void**)&W2th, g_W2th); cudaGetSymbolAddress((void**)&W2tl, g_W2tl);
    cudaGetSymbolAddress((void**)&hh, g_hh);     cudaGetSymbolAddress((void**)&hl, g_hl);

    cudaFuncSetAttribute(gemm_ts_kernel<0>, cudaFuncAttributeMaxDynamicSharedMemorySize, GEMM_SMEM);
    cudaFuncSetAttribute(gemm_ts_kernel<1>, cudaFuncAttributeMaxDynamicSharedMemorySize, GEMM_SMEM);
    cudaFuncSetAttribute(gemm_ts_kernel<2>, cudaFuncAttributeMaxDynamicSharedMemorySize, GEMM_SMEM);

    topk_softmax_kernel<<<2, 256>>>(l1, l2);

    {
        size_t n4 = (size_t)BS * DIM_D / 4;
        conv_split_kernel<<<(unsigned)((n4 + 255) / 256), 256>>>(x, xh, xl, n4);
        n4 = (size_t)DIM_D * KR / 4;
        gather_A_kernel<<<(unsigned)((n4 + 255) / 256), 256>>>(fc1_A, Ab1h, Ab1l, DIM_D, 0);
        n4 = (size_t)DIM_F * KR / 4;
        gather_A_kernel<<<(unsigned)((n4 + 255) / 256), 256>>>(fc2_A, Ab2h, Ab2l, DIM_F, 1);
        gather_Bt_kernel<<<dim3(DIM_F / 64, TOPK), 256>>>(fc1_B, Bb1th, Bb1tl, DIM_F, 0);
        gather_Bt_kernel<<<dim3(DIM_D / 64, TOPK), 256>>>(fc2_B, Bb2th, Bb2tl, DIM_D, 1);
    }

    // W1t (F x D) = Bb1t (F x KR) @ Ab1 (D x KR)^T
    gemm_ts_kernel<1><<<dim3(DIM_D / 256, DIM_F / 128), 256, GEMM_SMEM>>>(
        Bb1th, Bb1tl, Ab1h, Ab1l, KR, DIM_D, nullptr, W1th, W1tl);
    // W2t (D x F) = Bb2t (D x KR) @ Ab2 (F x KR)^T
    gemm_ts_kernel<1><<<dim3(DIM_F / 256, DIM_D / 128), 256, GEMM_SMEM>>>(
        Bb2th, Bb2tl, Ab2h, Ab2l, KR, DIM_F, nullptr, W2th, W2tl);
    // h (BS x F) = gelu( x (BS x D) @ W1t (F x D)^T )
    gemm_ts_kernel<2><<<dim3(DIM_F / 256, BS / 128), 256, GEMM_SMEM>>>(
        xh, xl, W1th, W1tl, DIM_D, DIM_F, nullptr, hh, hl);
    // out (BS x D) = h (BS x F) @ W2t (D x F)^T
    gemm_ts_kernel<0><<<dim3(DIM_D / 256, BS / 128), 256, GEMM_SMEM>>>(
        hh, hl, W2th, W2tl, DIM_F, DIM_D, out, nullptr, nullptr);
}

// round 4
// speedup vs baseline: 7.1686x; 1.3692x over previous
#include <cuda_runtime.h>
#include <cuda_bf16.h>
#include <math.h>
#include <stdint.h>

// ---------------------------------------------------------------------------
// Problem constants: B=2, S=1024, D=1024, F=4096, P=256, R=64, K=32.
// ---------------------------------------------------------------------------
#define DIM_D 1024
#define DIM_F 4096
#define DIM_P 256
#define DIM_R 64
#define TOPK  32
#define BS    2048
#define KR    (TOPK * DIM_R)   // 2048

// ---------------------------------------------------------------------------
// Feature detection: tcgen05 only exists on the sm_103a ("ALL") target.
// Plain compute_103 pass gets an FFMA fallback with identical semantics.
// ---------------------------------------------------------------------------
#if defined(__CUDA_ARCH__)
#  ifdef __CUDA_ARCH_HAS_FEATURE__
#    if __CUDA_ARCH_HAS_FEATURE__(SM103_ALL)
#      define TC_PATH 1
#    endif
#  endif
#  ifndef TC_PATH
#    ifdef __CUDA_ARCH_FEAT_SM103_ALL
#      define TC_PATH 1
#    else
#      define TC_PATH 0
#    endif
#  endif
#else
#  define TC_PATH 0
#endif

// ---------------------------------------------------------------------------
// PTX helpers
// ---------------------------------------------------------------------------
__device__ __forceinline__ uint32_t smem_to_u32(const void* smem_ptr) {
    uint32_t addr;
    asm("{ .reg .u64 tmp; cvta.to.shared.u64 tmp, %1; cvt.u32.u64 %0, tmp; }"
        : "=r"(addr) : "l"(smem_ptr));
    return addr;
}
#define SMEM_SWIZZLE_128B(byte_offset) \
    ((byte_offset) ^ (((byte_offset) >> 3) & 0x70))

#if TC_PATH
__device__ __forceinline__ uint32_t elect_one_pred() {
    uint32_t pred;
    asm volatile(
        "{\n\t.reg .pred p;\n\telect.sync _|p, 0xFFFFFFFF;\n\tselp.b32 %0, 1, 0, p;\n\t}"
        : "=r"(pred));
    return pred;
}

static constexpr uint64_t SMEM_DESC_BASE_SW128 =
    (uint64_t(2)  << 61) | (uint64_t(1) << 46) | (uint64_t(64) << 32) | (uint64_t(1) << 16);
#define MAKE_SMEM_DESC(base_addr) \
    (SMEM_DESC_BASE_SW128 | ((uint64_t)((base_addr) >> 4) & 0x3FFF))

#define TCGEN05_ALLOC(smem_result_addr, nCols) \
    asm volatile("tcgen05.alloc.cta_group::1.sync.aligned.shared::cta.b32 [%0], %1;" \
        :: "r"((uint32_t)(smem_result_addr)), "r"((uint32_t)(nCols)) : "memory")
#define TCGEN05_DEALLOC(tmem_addr, nCols) \
    asm volatile("tcgen05.dealloc.cta_group::1.sync.aligned.b32 %0, %1;" \
        :: "r"(tmem_addr), "r"((uint32_t)(nCols)))
#define TCGEN05_RELINQUISH_ALLOC_PERMIT() \
    asm volatile("tcgen05.relinquish_alloc_permit.cta_group::1.sync.aligned;")
#define TCGEN05_COMMIT(mbar_smem_addr) \
    asm volatile("tcgen05.commit.cta_group::1.mbarrier::arrive::one.shared::cluster.b64 [%0];" \
        :: "r"((uint32_t)(mbar_smem_addr)) : "memory")
#define TCGEN05_FENCE_AFTER() \
    asm volatile("tcgen05.fence::after_thread_sync;" ::: "memory")
#define TCGEN05_FENCE_BEFORE() \
    asm volatile("tcgen05.fence::before_thread_sync;" ::: "memory")
#define TCGEN05_WAIT_LD() \
    asm volatile("tcgen05.wait::ld.sync.aligned;" ::: "memory")
#define FENCE_PROXY_ASYNC_SHARED_CTA() \
    asm volatile("fence.proxy.async.shared::cta;" ::: "memory")
#define MBARRIER_INIT(mbar_smem_addr, count) \
    asm volatile("mbarrier.init.shared.b64 [%0], %1;" \
        :: "r"((uint32_t)(mbar_smem_addr)), "r"((uint32_t)(count)) : "memory")
#define MBARRIER_WAIT_PARITY(mbar_smem_addr, phase_parity) do { \
    uint32_t _mbar = (uint32_t)(mbar_smem_addr); \
    uint32_t _parity = (uint32_t)(phase_parity); \
    uint32_t _done; \
    asm volatile( \
        "{\n\t.reg .pred p;\n\t" \
        "mbarrier.try_wait.parity.acquire.cta.shared::cta.b64 p, [%1], %2;\n\t" \
        "selp.b32 %0, 1, 0, p;\n\t}" \
        : "=r"(_done) : "r"(_mbar), "r"(_parity) : "memory"); \
    if (!_done) { \
        asm volatile( \
            "{\n\t.reg .pred P1;\n\t" \
            "WAIT_LOOP_%=:\n\t" \
            "mbarrier.try_wait.parity.acquire.cta.shared::cta.b64 P1, [%0], %1, 0x989680;\n\t" \
            "@P1 bra.uni WAIT_DONE_%=;\n\t" \
            "bra.uni WAIT_LOOP_%=;\n\t" \
            "WAIT_DONE_%=:\n\t}" \
            :: "r"(_mbar), "r"(_parity) : "memory"); \
    } \
} while(0)

#define CP_ASYNC16(dst_u32, src_ptr) \
    asm volatile("cp.async.cg.shared.global [%0], [%1], 16;" \
        :: "r"(dst_u32), "l"(src_ptr) : "memory")
#define CP_COMMIT()  asm volatile("cp.async.commit_group;" ::: "memory")
#define CP_WAIT0()   asm volatile("cp.async.wait_group 0;" ::: "memory")

#define TCGEN05_LD_32X32B_X32(r, tmem_addr) \
    asm volatile( \
        "tcgen05.ld.sync.aligned.32x32b.x32.b32 " \
        "{%0, %1, %2, %3, %4, %5, %6, %7, " \
        " %8, %9, %10, %11, %12, %13, %14, %15, " \
        " %16, %17, %18, %19, %20, %21, %22, %23, " \
        " %24, %25, %26, %27, %28, %29, %30, %31}, [%32];" \
        : "=r"((r)[0]),  "=r"((r)[1]),  "=r"((r)[2]),  "=r"((r)[3]), \
          "=r"((r)[4]),  "=r"((r)[5]),  "=r"((r)[6]),  "=r"((r)[7]), \
          "=r"((r)[8]),  "=r"((r)[9]),  "=r"((r)[10]), "=r"((r)[11]), \
          "=r"((r)[12]), "=r"((r)[13]), "=r"((r)[14]), "=r"((r)[15]), \
          "=r"((r)[16]), "=r"((r)[17]), "=r"((r)[18]), "=r"((r)[19]), \
          "=r"((r)[20]), "=r"((r)[21]), "=r"((r)[22]), "=r"((r)[23]), \
          "=r"((r)[24]), "=r"((r)[25]), "=r"((r)[26]), "=r"((r)[27]), \
          "=r"((r)[28]), "=r"((r)[29]), "=r"((r)[30]), "=r"((r)[31]) \
        : "r"(tmem_addr))

// SS-mode cg1 kind::f16 MMA (bf16 in, f32 accum), M=128, N=256.
__device__ __forceinline__ void mma_f16_ss(uint32_t d_tmem, uint64_t a_desc,
                                           uint64_t b_desc, uint32_t idesc, bool en) {
    uint32_t e = en ? 1u : 0u;
    asm volatile(
        "{\n\t.reg .pred p;\n\tsetp.ne.u32 p, %4, 0;\n\t"
        "tcgen05.mma.cta_group::1.kind::f16 [%0], %1, %2, %3, {%5, %5, %5, %5}, p;\n\t}"
        :: "r"(d_tmem), "l"(a_desc), "l"(b_desc), "r"(idesc), "r"(e), "r"(0u)
        : "memory");
}

// idesc: dtype=F32(bit4), atype=BF16(bit7), btype=BF16(bit10), N/8@[17:22], M/16@[24:28]
static constexpr uint32_t IDESC_128x256 =
    (1u << 4) | (1u << 7) | (1u << 10) | ((256u / 8u) << 17) | ((128u / 16u) << 24);
#endif  // TC_PATH

// ---------------------------------------------------------------------------
// Device scratch (bf16 hi/lo split buffers + split-K partials)
// ---------------------------------------------------------------------------
__device__ int   g_idx[2][TOPK];
__device__ float g_wgt[2][TOPK];

__device__ __nv_bfloat16 g_xh[(size_t)BS * DIM_D];
__device__ __nv_bfloat16 g_xl[(size_t)BS * DIM_D];
__device__ __nv_bfloat16 g_Ab1h[(size_t)DIM_D * KR];
__device__ __nv_bfloat16 g_Ab1l[(size_t)DIM_D * KR];
__device__ __nv_bfloat16 g_Bb1th[(size_t)DIM_F * KR];
__device__ __nv_bfloat16 g_Bb1tl[(size_t)DIM_F * KR];
__device__ __nv_bfloat16 g_Ab2h[(size_t)DIM_F * KR];
__device__ __nv_bfloat16 g_Ab2l[(size_t)DIM_F * KR];
__device__ __nv_bfloat16 g_Bb2th[(size_t)DIM_D * KR];
__device__ __nv_bfloat16 g_Bb2tl[(size_t)DIM_D * KR];
__device__ __nv_bfloat16 g_W1th[(size_t)DIM_F * DIM_D];
__device__ __nv_bfloat16 g_W1tl[(size_t)DIM_F * DIM_D];
__device__ __nv_bfloat16 g_W2th[(size_t)DIM_D * DIM_F];
__device__ __nv_bfloat16 g_W2tl[(size_t)DIM_D * DIM_F];
__device__ __nv_bfloat16 g_hh[(size_t)BS * DIM_F];
__device__ __nv_bfloat16 g_hl[(size_t)BS * DIM_F];
__device__ float g_p0[(size_t)BS * DIM_D];
__device__ float g_p1[(size_t)BS * DIM_D];

__device__ __forceinline__ void split_bf16(float v, __nv_bfloat16& h, __nv_bfloat16& l) {
    h = __float2bfloat16(v);
    l = __float2bfloat16(v - __bfloat162float(h));
}

// ---------------------------------------------------------------------------
// Top-K + softmax: one warp per FC. Each lane owns 8 logits in registers.
// ---------------------------------------------------------------------------
__global__ void topk_softmax_kernel(const float* __restrict__ logits1,
                                    const float* __restrict__ logits2) {
    const float* logits = (blockIdx.x == 0) ? logits1 : logits2;
    int which = blockIdx.x;
    int lane = threadIdx.x;   // 0..31
    float v[8];
    #pragma unroll
    for (int j = 0; j < 8; j++) v[j] = logits[lane * 8 + j];

    __shared__ float vals[TOPK];
    for (int k = 0; k < TOPK; k++) {
        // local argmax (strict > keeps lowest index on ties)
        float bv = v[0]; int bj = 0;
        #pragma unroll
        for (int j = 1; j < 8; j++) if (v[j] > bv) { bv = v[j]; bj = j; }
        int bidx = lane * 8 + bj;
        // warp argmax, prefer lower global index on equal value
        #pragma unroll
        for (int s = 16; s > 0; s >>= 1) {
            float ov = __shfl_xor_sync(0xFFFFFFFF, bv, s);
            int   oi = __shfl_xor_sync(0xFFFFFFFF, bidx, s);
            if (ov > bv || (ov == bv && oi < bidx)) { bv = ov; bidx = oi; }
        }
        if (lane == 0) { g_idx[which][k] = bidx; vals[k] = bv; }
        if (bidx >> 3 == lane) v[bidx & 7] = -3.402823466e38f;
    }
    __syncwarp();
    if (lane == 0) {
        float mx = -3.402823466e38f;
        #pragma unroll
        for (int k = 0; k < TOPK; k++) mx = fmaxf(mx, vals[k]);
        float e[TOPK]; float sum = 0.f;
        #pragma unroll
        for (int k = 0; k < TOPK; k++) { e[k] = expf(vals[k] - mx); sum += e[k]; }
        float inv = 1.f / sum;
        #pragma unroll
        for (int k = 0; k < TOPK; k++) g_wgt[which][k] = e[k] * inv;
    }
}

// ---------------------------------------------------------------------------
// Scaled A gather -> bf16 hi/lo: out (d_in, KR). 16 floats / thread.
// ---------------------------------------------------------------------------
__global__ void gather_A_kernel(const float* __restrict__ A,
                                __nv_bfloat16* __restrict__ hi,
                                __nv_bfloat16* __restrict__ lo,
                                int d_in, int which) {
    size_t vidx = (size_t)blockIdx.x * blockDim.x + threadIdx.x;
    size_t i = vidx * 16;
    if (i >= (size_t)d_in * KR) return;
    int d = (int)(i >> 11);
    int c = (int)(i & 2047);
    int k = c >> 6;
    int r = c & 63;           // multiple of 16
    int p = g_idx[which][k];
    float w = g_wgt[which][k];
    const float* src = A + ((size_t)p * d_in + d) * DIM_R + r;
    float4 s0 = *reinterpret_cast<const float4*>(src + 0);
    float4 s1 = *reinterpret_cast<const float4*>(src + 4);
    float4 s2 = *reinterpret_cast<const float4*>(src + 8);
    float4 s3 = *reinterpret_cast<const float4*>(src + 12);
    float f[16] = {s0.x,s0.y,s0.z,s0.w, s1.x,s1.y,s1.z,s1.w,
                   s2.x,s2.y,s2.z,s2.w, s3.x,s3.y,s3.z,s3.w};
    union { __nv_bfloat16 b[8]; uint4 u; } h0, h1, l0, l1;
    #pragma unroll
    for (int e = 0; e < 8; e++)  split_bf16(w * f[e],     h0.b[e], l0.b[e]);
    #pragma unroll
    for (int e = 0; e < 8; e++)  split_bf16(w * f[8 + e], h1.b[e], l1.b[e]);
    *reinterpret_cast<uint4*>(hi + i)     = h0.u;
    *reinterpret_cast<uint4*>(hi + i + 8) = h1.u;
    *reinterpret_cast<uint4*>(lo + i)     = l0.u;
    *reinterpret_cast<uint4*>(lo + i + 8) = l1.u;
}

// ---------------------------------------------------------------------------
// Transposed B gather -> bf16 hi/lo: out (d_out, KR), out[f][k*64+r] = B[p_k][r][f]
// float4 gmem loads, smem transpose, uint4 stores.
// ---------------------------------------------------------------------------
__global__ void gather_Bt_kernel(const float* __restrict__ B,
                                 __nv_bfloat16* __restrict__ hi,
                                 __nv_bfloat16* __restrict__ lo,
                                 int d_out, int which) {
    __shared__ float tile[64][65];
    int k  = blockIdx.y;
    int f0 = blockIdx.x * 64;
    int p  = g_idx[which][k];
    int tid = threadIdx.x;
    const float* src = B + (size_t)p * DIM_R * d_out + f0;
    #pragma unroll
    for (int j = 0; j < 4; j++) {
        int id = tid + 256 * j;          // 0..1023
        int r = id >> 4;                 // 0..63
        int f4 = (id & 15) * 4;          // 0..60
        float4 v = *reinterpret_cast<const float4*>(src + (size_t)r * d_out + f4);
        tile[r][f4 + 0] = v.x; tile[r][f4 + 1] = v.y;
        tile[r][f4 + 2] = v.z; tile[r][f4 + 3] = v.w;
    }
    __syncthreads();
    int ow = tid >> 2, seg = tid & 3;
    union { __nv_bfloat16 b[8]; uint4 u; } uh0, uh1, ul0, ul1;
    #pragma unroll
    for (int e = 0; e < 16; e++) {
        float v = tile[seg * 16 + e][ow];
        __nv_bfloat16 h, l; split_bf16(v, h, l);
        if (e < 8) { uh0.b[e] = h; ul0.b[e] = l; }
        else       { uh1.b[e - 8] = h; ul1.b[e - 8] = l; }
    }
    size_t o = (size_t)(f0 + ow) * KR + (size_t)k * 64 + (size_t)seg * 16;
    *reinterpret_cast<uint4*>(hi + o)     = uh0.u;
    *reinterpret_cast<uint4*>(hi + o + 8) = uh1.u;
    *reinterpret_cast<uint4*>(lo + o)     = ul0.u;
    *reinterpret_cast<uint4*>(lo + o + 8) = ul1.u;
}

// ---------------------------------------------------------------------------
// Elementwise fp32 -> bf16 hi/lo split, 16 floats / thread
// ---------------------------------------------------------------------------
__global__ void conv_split_kernel(const float* __restrict__ in,
                                  __nv_bfloat16* __restrict__ hi,
                                  __nv_bfloat16* __restrict__ lo,
                                  size_t total) {
    size_t i = ((size_t)blockIdx.x * blockDim.x + threadIdx.x) * 16;
    if (i >= total) return;
    float4 s0 = *reinterpret_cast<const float4*>(in + i + 0);
    float4 s1 = *reinterpret_cast<const float4*>(in + i + 4);
    float4 s2 = *reinterpret_cast<const float4*>(in + i + 8);
    float4 s3 = *reinterpret_cast<const float4*>(in + i + 12);
    float f[16] = {s0.x,s0.y,s0.z,s0.w, s1.x,s1.y,s1.z,s1.w,
                   s2.x,s2.y,s2.z,s2.w, s3.x,s3.y,s3.z,s3.w};
    union { __nv_bfloat16 b[8]; uint4 u; } h0, h1, l0, l1;
    #pragma unroll
    for (int e = 0; e < 8; e++)  split_bf16(f[e],     h0.b[e], l0.b[e]);
    #pragma unroll
    for (int e = 0; e < 8; e++)  split_bf16(f[8 + e], h1.b[e], l1.b[e]);
    *reinterpret_cast<uint4*>(hi + i)     = h0.u;
    *reinterpret_cast<uint4*>(hi + i + 8) = h1.u;
    *reinterpret_cast<uint4*>(lo + i)     = l0.u;
    *reinterpret_cast<uint4*>(lo + i + 8) = l1.u;
}

__global__ void add_kernel(const float* __restrict__ a, const float* __restrict__ b,
                           float* __restrict__ out, size_t total4) {
    size_t vidx = (size_t)blockIdx.x * blockDim.x + threadIdx.x;
    if (vidx >= total4) return;
    float4 x = reinterpret_cast<const float4*>(a)[vidx];
    float4 y = reinterpret_cast<const float4*>(b)[vidx];
    reinterpret_cast<float4*>(out)[vidx] =
        make_float4(x.x + y.x, x.y + y.y, x.z + y.z, x.w + y.w);
}

__device__ __forceinline__ float gelu_tanh(float x) {
    const float c0 = 0.7978845608028654f;
    const float c1 = 0.044715f;
    float x3 = x * x * x;
    return 0.5f * x * (1.0f + tanhf(c0 * (x + c1 * x3)));
}

// ---------------------------------------------------------------------------
// GEMM body: D(128,256) tile of (Ahi+Alo)(M,Ks) @ [(Bhi+Blo)(N,Ks)]^T
// over K range [Koff, Koff+Klen). K-major bf16 operands.
// EPI: 0 fp32, 1 bf16 hi/lo, 2 gelu + bf16 hi/lo.
// ---------------------------------------------------------------------------
#define STAGE_BYTES 98304
#define OFF_TILES   1024
#define GEMM_SMEM   (OFF_TILES + 2 * STAGE_BYTES)   // 197632

template <int EPI>
__device__ __forceinline__ void gemm_body(
    const __nv_bfloat16* __restrict__ Ahi, const __nv_bfloat16* __restrict__ Alo,
    const __nv_bfloat16* __restrict__ Bhi, const __nv_bfloat16* __restrict__ Blo,
    int Kstride, int Koff, int Klen, int N_total,
    float* __restrict__ outF, __nv_bfloat16* __restrict__ outHi,
    __nv_bfloat16* __restrict__ outLo, int m0, int n0, char* smem) {
    int tid = threadIdx.x;
#if TC_PATH
    uint32_t sb = smem_to_u32(smem);
    int wid = tid >> 5;
    int lid = tid & 31;

    if (wid == 0) TCGEN05_ALLOC(sb + 0, 256);
    if (tid == 0) { MBARRIER_INIT(sb + 8, 1); MBARRIER_INIT(sb + 16, 1); }
    __syncthreads();
    uint32_t tmem;
    asm volatile("ld.shared.b32 %0, [%1];" : "=r"(tmem) : "r"(sb + 0));

    int ph0 = 0, ph1 = 0;
    int NC = Klen >> 6;

    // per-thread fixed load coordinates
    int arow = tid >> 1;                 // with i-offset below
    (void)arow;

    #pragma unroll 1
    for (int s = 0; s < NC; s++) {
        int st = s & 1;
        if (s >= 2) {
            if (st == 0) { MBARRIER_WAIT_PARITY(sb + 8, ph0 & 1); ph0++; }
            else         { MBARRIER_WAIT_PARITY(sb + 16, ph1 & 1); ph1++; }
        }
        int k0 = Koff + (s << 6);
        uint32_t stage = sb + OFF_TILES + st * STAGE_BYTES;
        // A tiles: 128 rows x 128B (hi @ +0, lo @ +16384)
        #pragma unroll
        for (int i = 0; i < 4; i++) {
            int cid = tid + 256 * i;
            int row = cid >> 3, c16 = cid & 7;
            size_t go = ((size_t)(m0 + row) * Kstride + k0) * 2 + c16 * 16;
            uint32_t sw = SMEM_SWIZZLE_128B((uint32_t)(row * 128 + c16 * 16));
            CP_ASYNC16(stage + sw,         (const char*)Ahi + go);
            CP_ASYNC16(stage + 16384 + sw, (const char*)Alo + go);
        }
        // B tiles: 256 rows x 128B (hi @ +32768, lo @ +65536)
        #pragma unroll
        for (int i = 0; i < 8; i++) {
            int cid = tid + 256 * i;
            int row = cid >> 3, c16 = cid & 7;
            size_t go = ((size_t)(n0 + row) * Kstride + k0) * 2 + c16 * 16;
            uint32_t sw = SMEM_SWIZZLE_128B((uint32_t)(row * 128 + c16 * 16));
            CP_ASYNC16(stage + 32768 + sw, (const char*)Bhi + go);
            CP_ASYNC16(stage + 65536 + sw, (const char*)Blo + go);
        }
        CP_COMMIT();
        CP_WAIT0();
        FENCE_PROXY_ASYNC_SHARED_CTA();
        __syncthreads();

        if (wid == 0 && elect_one_pred()) {
            uint64_t dAh = MAKE_SMEM_DESC(stage);
            uint64_t dAl = MAKE_SMEM_DESC(stage + 16384);
            uint64_t dBh = MAKE_SMEM_DESC(stage + 32768);
            uint64_t dBl = MAKE_SMEM_DESC(stage + 65536);
            #pragma unroll
            for (int c = 0; c < 3; c++) {
                uint64_t dA = (c == 2) ? dAl : dAh;
                uint64_t dB = (c == 1) ? dBl : dBh;
                #pragma unroll
                for (int ks = 0; ks < 4; ks++) {
                    bool en = !(s == 0 && c == 0 && ks == 0);
                    mma_f16_ss(tmem, dA + ks * 2, dB + ks * 2, IDESC_128x256, en);
                }
            }
            TCGEN05_COMMIT(sb + 8 + st * 8);
        }
    }

    MBARRIER_WAIT_PARITY(sb + 8, ph0 & 1);
    MBARRIER_WAIT_PARITY(sb + 16, ph1 & 1);
    TCGEN05_FENCE_AFTER();

    if (wid < 4) {
        int row = m0 + wid * 32 + lid;
        #pragma unroll 1
        for (int nb = 0; nb < 8; nb++) {
            uint32_t r[32];
            TCGEN05_LD_32X32B_X32(r, tmem + nb * 32);
            TCGEN05_WAIT_LD();
            int nc0 = n0 + nb * 32;
            if (EPI == 0) {
                #pragma unroll
                for (int j = 0; j < 8; j++) {
                    float4 o = make_float4(__uint_as_float(r[4 * j + 0]),
                                           __uint_as_float(r[4 * j + 1]),
                                           __uint_as_float(r[4 * j + 2]),
                                           __uint_as_float(r[4 * j + 3]));
                    *reinterpret_cast<float4*>(outF + (size_t)row * N_total + nc0 + 4 * j) = o;
                }
            } else {
                #pragma unroll
                for (int j = 0; j < 4; j++) {
                    union { __nv_bfloat16 b[8]; uint4 u; } uh, ul;
                    #pragma unroll
                    for (int e = 0; e < 8; e++) {
                        float v = __uint_as_float(r[8 * j + e]);
                        if (EPI == 2) v = gelu_tanh(v);
                        split_bf16(v, uh.b[e], ul.b[e]);
                    }
                    size_t o = (size_t)row * N_total + nc0 + 8 * j;
                    *reinterpret_cast<uint4*>(outHi + o) = uh.u;
                    *reinterpret_cast<uint4*>(outLo + o) = ul.u;
                }
            }
        }
        TCGEN05_FENCE_BEFORE();
    }

    __syncthreads();
    if (wid == 0) {
        TCGEN05_RELINQUISH_ALLOC_PERMIT();
        TCGEN05_DEALLOC(tmem, 256);
    }
#else
    // ---------------- FFMA fallback (no tcgen05 on this target) ------------
    float* As = reinterpret_cast<float*>(smem);             // [16][132]
    float* Bs = reinterpret_cast<float*>(smem) + 16 * 132;  // [16][68]
    int tx = tid & 15;
    int ty = tid >> 4;

    #pragma unroll 1
    for (int nchunk = 0; nchunk < 4; nchunk++) {
        int nbase = n0 + nchunk * 64;
        float acc[8][4];
        #pragma unroll
        for (int i = 0; i < 8; i++)
            #pragma unroll
            for (int j = 0; j < 4; j++) acc[i][j] = 0.f;

        #pragma unroll 1
        for (int k0 = Koff; k0 < Koff + Klen; k0 += 16) {
            {
                int row = tid >> 1;
                int kseg = (tid & 1) * 8;
                size_t go = (size_t)(m0 + row) * Kstride + k0 + kseg;
                union { uint4 u; __nv_bfloat16 b[8]; } vh, vl;
                vh.u = *reinterpret_cast<const uint4*>(Ahi + go);
                vl.u = *reinterpret_cast<const uint4*>(Alo + go);
                #pragma unroll
                for (int e = 0; e < 8; e++)
                    As[(kseg + e) * 132 + row] =
                        __bfloat162float(vh.b[e]) + __bfloat162float(vl.b[e]);
            }
            {
                int row = tid >> 2;
                int kseg = (tid & 3) * 4;
                size_t go = (size_t)(nbase + row) * Kstride + k0 + kseg;
                union { uint2 u; __nv_bfloat16 b[4]; } vh, vl;
                vh.u = *reinterpret_cast<const uint2*>(Bhi + go);
                vl.u = *reinterpret_cast<const uint2*>(Blo + go);
                #pragma unroll
                for (int e = 0; e < 4; e++)
                    Bs[(kseg + e) * 68 + row] =
                        __bfloat162float(vh.b[e]) + __bfloat162float(vl.b[e]);
            }
            __syncthreads();
            #pragma unroll
            for (int kk = 0; kk < 16; kk++) {
                float a0[8], b0[4];
                float4 a4a = *reinterpret_cast<const float4*>(&As[kk * 132 + ty * 8]);
                float4 a4b = *reinterpret_cast<const float4*>(&As[kk * 132 + ty * 8 + 4]);
                float4 b4  = *reinterpret_cast<const float4*>(&Bs[kk * 68 + tx * 4]);
                a0[0]=a4a.x; a0[1]=a4a.y; a0[2]=a4a.z; a0[3]=a4a.w;
                a0[4]=a4b.x; a0[5]=a4b.y; a0[6]=a4b.z; a0[7]=a4b.w;
                b0[0]=b4.x;  b0[1]=b4.y;  b0[2]=b4.z;  b0[3]=b4.w;
                #pragma unroll
                for (int i = 0; i < 8; i++)
                    #pragma unroll
                    for (int j = 0; j < 4; j++)
                        acc[i][j] = fmaf(a0[i], b0[j], acc[i][j]);
            }
            __syncthreads();
        }

        #pragma unroll
        for (int i = 0; i < 8; i++) {
            int row = m0 + ty * 8 + i;
            int col = nbase + tx * 4;
            if (EPI == 0) {
                float4 o = make_float4(acc[i][0], acc[i][1], acc[i][2], acc[i][3]);
                *reinterpret_cast<float4*>(outF + (size_t)row * N_total + col) = o;
            } else {
                union { __nv_bfloat16 b[4]; uint2 u; } uh, ul;
                #pragma unroll
                for (int j = 0; j < 4; j++) {
                    float v = acc[i][j];
                    if (EPI == 2) v = gelu_tanh(v);
                    split_bf16(v, uh.b[j], ul.b[j]);
                }
                size_t o = (size_t)row * N_total + col;
                *reinterpret_cast<uint2*>(outHi + o) = uh.u;
                *reinterpret_cast<uint2*>(outLo + o) = ul.u;
            }
        }
    }
#endif
}

// ---------------------------------------------------------------------------
// GEMM wrappers
// ---------------------------------------------------------------------------
// Fused compose: blockIdx.x < 128 -> W1t (M=4096, N=1024), else W2t (M=1024, N=4096)
__global__ void __launch_bounds__(256, 1)
compose_fused_kernel(const __nv_bfloat16* A1h, const __nv_bfloat16* A1l,
                     const __nv_bfloat16* B1h, const __nv_bfloat16* B1l,
                     __nv_bfloat16* o1h, __nv_bfloat16* o1l,
                     const __nv_bfloat16* A2h, const __nv_bfloat16* A2l,
                     const __nv_bfloat16* B2h, const __nv_bfloat16* B2l,
                     __nv_bfloat16* o2h, __nv_bfloat16* o2l) {
    extern __shared__ __align__(1024) char smem[];
    int b = blockIdx.x;
    if (b < 128) {
        int n0 = (b & 3) * 256;        // 4 n-tiles (N=1024)
        int m0 = (b >> 2) * 128;       // 32 m-tiles (M=4096)
        gemm_body<1>(A1h, A1l, B1h, B1l, KR, 0, KR, DIM_D,
                     nullptr, o1h, o1l, m0, n0, smem);
    } else {
        b -= 128;
        int n0 = (b & 15) * 256;       // 16 n-tiles (N=4096)
        int m0 = (b >> 4) * 128;       // 8 m-tiles (M=1024)
        gemm_body<1>(A2h, A2l, B2h, B2l, KR, 0, KR, DIM_F,
                     nullptr, o2h, o2l, m0, n0, smem);
    }
}

// Generic single GEMM, EPI templated. gridDim = (ntiles, mtiles)
template <int EPI>
__global__ void __launch_bounds__(256, 1)
gemm_kernel(const __nv_bfloat16* Ahi, const __nv_bfloat16* Alo,
            const __nv_bfloat16* Bhi, const __nv_bfloat16* Blo,
            int Kstride, int Koff, int Klen, int N_total,
            float* outF, __nv_bfloat16* outHi, __nv_bfloat16* outLo) {
    extern __shared__ __align__(1024) char smem[];
    gemm_body<EPI>(Ahi, Alo, Bhi, Blo, Kstride, Koff, Klen, N_total,
                   outF, outHi, outLo, blockIdx.y * 128, blockIdx.x * 256, smem);
}

// Split-K GEMM for the final output: z selects K half and partial buffer.
__global__ void __launch_bounds__(256, 1)
gemm_splitk_kernel(const __nv_bfloat16* Ahi, const __nv_bfloat16* Alo,
                   const __nv_bfloat16* Bhi, const __nv_bfloat16* Blo,
                   int Kstride, int N_total, float* p0, float* p1) {
    extern __shared__ __align__(1024) char smem[];
    int z = blockIdx.z;
    gemm_body<0>(Ahi, Alo, Bhi, Blo, Kstride, z * (Kstride / 2), Kstride / 2,
                 N_total, z ? p1 : p0, nullptr, nullptr,
                 blockIdx.y * 128, blockIdx.x * 256, smem);
}

// ---------------------------------------------------------------------------
// Launch
// ---------------------------------------------------------------------------
extern "C" void kernel_launch(void* const* d_in, const int* in_sizes, int n_in,
                              void* d_out, int out_size) {
    const float* x     = (const float*)d_in[0];
    const float* fc1_A = (const float*)d_in[1];
    const float* fc1_B = (const float*)d_in[2];
    const float* fc2_A = (const float*)d_in[3];
    const float* fc2_B = (const float*)d_in[4];
    const float* l1    = (const float*)d_in[5];
    const float* l2    = (const float*)d_in[6];
    float* out = (float*)d_out;

    __nv_bfloat16 *xh, *xl, *Ab1h, *Ab1l, *Bb1th, *Bb1tl, *Ab2h, *Ab2l,
                  *Bb2th, *Bb2tl, *W1th, *W1tl, *W2th, *W2tl, *hh, *hl;
    float *p0, *p1;
    cudaGetSymbolAddress((void**)&xh, g_xh);     cudaGetSymbolAddress((void**)&xl, g_xl);
    cudaGetSymbolAddress((void**)&Ab1h, g_Ab1h); cudaGetSymbolAddress((void**)&Ab1l, g_Ab1l);
    cudaGetSymbolAddress((void**)&Bb1th, g_Bb1th); cudaGetSymbolAddress((void**)&Bb1tl, g_Bb1tl);
    cudaGetSymbolAddress((void**)&Ab2h, g_Ab2h); cudaGetSymbolAddress((void**)&Ab2l, g_Ab2l);
    cudaGetSymbolAddress((void**)&Bb2th, g_Bb2th); cudaGetSymbolAddress((void**)&Bb2tl, g_Bb2tl);
    cudaGetSymbolAddress((void**)&W1th, g_W1th); cudaGetSymbolAddress((void**)&W1tl, g_W1tl);
    cudaGetSymbolAddress((void**)&W2th, g_W2th); cudaGetSymbolAddress((void**)&W2tl, g_W2tl);
    cudaGetSymbolAddress((void**)&hh, g_hh);     cudaGetSymbolAddress((void**)&hl, g_hl);
    cudaGetSymbolAddress((void**)&p0, g_p0);     cudaGetSymbolAddress((void**)&p1, g_p1);

    cudaFuncSetAttribute(compose_fused_kernel, cudaFuncAttributeMaxDynamicSharedMemorySize, GEMM_SMEM);
    cudaFuncSetAttribute(gemm_kernel<2>, cudaFuncAttributeMaxDynamicSharedMemorySize, GEMM_SMEM);
    cudaFuncSetAttribute(gemm_splitk_kernel, cudaFuncAttributeMaxDynamicSharedMemorySize, GEMM_SMEM);

    topk_softmax_kernel<<<2, 32>>>(l1, l2);

    {
        conv_split_kernel<<<(BS * DIM_D / 16 + 255) / 256, 256>>>(x, xh, xl, (size_t)BS * DIM_D);
        gather_A_kernel<<<(DIM_D * KR / 16 + 255) / 256, 256>>>(fc1_A, Ab1h, Ab1l, DIM_D, 0);
        gather_A_kernel<<<(DIM_F * KR / 16 + 255) / 256, 256>>>(fc2_A, Ab2h, Ab2l, DIM_F, 1);
        gather_Bt_kernel<<<dim3(DIM_F / 64, TOPK), 256>>>(fc1_B, Bb1th, Bb1tl, DIM_F, 0);
        gather_Bt_kernel<<<dim3(DIM_D / 64, TOPK), 256>>>(fc2_B, Bb2th, Bb2tl, DIM_D, 1);
    }

    // Fused compose: W1t (F x D) and W2t (D x F), both over KR
    compose_fused_kernel<<<256, 256, GEMM_SMEM>>>(
        Bb1th, Bb1tl, Ab1h, Ab1l, W1th, W1tl,
        Bb2th, Bb2tl, Ab2h, Ab2l, W2th, W2tl);

    // h (BS x F) = gelu( x (BS x D) @ W1t (F x D)^T )
    gemm_kernel<2><<<dim3(DIM_F / 256, BS / 128), 256, GEMM_SMEM>>>(
        xh, xl, W1th, W1tl, DIM_D, 0, DIM_D, DIM_F, nullptr, hh, hl);

    // out (BS x D) = h (BS x F) @ W2t (D x F)^T  — split-K x2 + add
    gemm_splitk_kernel<<<dim3(DIM_D / 256, BS / 128, 2), 256, GEMM_SMEM>>>(
        hh, hl, W2th, W2tl, DIM_F, DIM_D, p0, p1);
    add_kernel<<<(BS * DIM_D / 4 + 255) / 256, 256>>>(p0, p1, out, (size_t)BS * DIM_D / 4);
}

// round 5
// speedup vs baseline: 8.2442x; 1.1501x over previous
#include <cuda_runtime.h>
#include <cuda_bf16.h>
#include <math.h>
#include <stdint.h>

// ---------------------------------------------------------------------------
// Problem constants: B=2, S=1024, D=1024, F=4096, P=256, R=64, K=32.
// ---------------------------------------------------------------------------
#define DIM_D 1024
#define DIM_F 4096
#define DIM_P 256
#define DIM_R 64
#define TOPK  32
#define BS    2048
#define KR    (TOPK * DIM_R)   // 2048

// ---------------------------------------------------------------------------
// Feature detection: tcgen05 only on sm_103a target; plain compute_103 pass
// gets an FFMA fallback with identical semantics.
// ---------------------------------------------------------------------------
#if defined(__CUDA_ARCH__)
#  ifdef __CUDA_ARCH_HAS_FEATURE__
#    if __CUDA_ARCH_HAS_FEATURE__(SM103_ALL)
#      define TC_PATH 1
#    endif
#  endif
#  ifndef TC_PATH
#    ifdef __CUDA_ARCH_FEAT_SM103_ALL
#      define TC_PATH 1
#    else
#      define TC_PATH 0
#    endif
#  endif
#else
#  define TC_PATH 0
#endif

// ---------------------------------------------------------------------------
// PTX helpers
// ---------------------------------------------------------------------------
__device__ __forceinline__ uint32_t smem_to_u32(const void* smem_ptr) {
    uint32_t addr;
    asm("{ .reg .u64 tmp; cvta.to.shared.u64 tmp, %1; cvt.u32.u64 %0, tmp; }"
        : "=r"(addr) : "l"(smem_ptr));
    return addr;
}
#define SMEM_SWIZZLE_128B(byte_offset) \
    ((byte_offset) ^ (((byte_offset) >> 3) & 0x70))

__device__ __forceinline__ uint32_t cluster_rank() {
    uint32_t r;
    asm("mov.u32 %0, %%cluster_ctarank;" : "=r"(r));
    return r;
}

#if TC_PATH
__device__ __forceinline__ uint32_t elect_one_pred() {
    uint32_t pred;
    asm volatile(
        "{\n\t.reg .pred p;\n\telect.sync _|p, 0xFFFFFFFF;\n\tselp.b32 %0, 1, 0, p;\n\t}"
        : "=r"(pred));
    return pred;
}

static constexpr uint64_t SMEM_DESC_BASE_SW128 =
    (uint64_t(2)  << 61) | (uint64_t(1) << 46) | (uint64_t(64) << 32) | (uint64_t(1) << 16);
#define MAKE_SMEM_DESC(base_addr) \
    (SMEM_DESC_BASE_SW128 | ((uint64_t)((base_addr) >> 4) & 0x3FFF))

#define TCGEN05_ALLOC_CG2(smem_result_addr, nCols) \
    asm volatile("tcgen05.alloc.cta_group::2.sync.aligned.shared::cta.b32 [%0], %1;" \
        :: "r"((uint32_t)(smem_result_addr)), "r"((uint32_t)(nCols)) : "memory")
#define TCGEN05_DEALLOC_CG2(tmem_addr, nCols) \
    asm volatile("tcgen05.dealloc.cta_group::2.sync.aligned.b32 %0, %1;" \
        :: "r"(tmem_addr), "r"((uint32_t)(nCols)))
#define TCGEN05_RELINQUISH_CG2() \
    asm volatile("tcgen05.relinquish_alloc_permit.cta_group::2.sync.aligned;")
#define TCGEN05_COMMIT_MULTICAST_CG2(mbar, mask) \
    asm volatile("tcgen05.commit.cta_group::2.mbarrier::arrive::one.shared::cluster.multicast::cluster.b64 [%0], %1;" \
        :: "r"((uint32_t)(mbar)), "h"((uint16_t)(mask)) : "memory")
#define TCGEN05_FENCE_AFTER() \
    asm volatile("tcgen05.fence::after_thread_sync;" ::: "memory")
#define TCGEN05_FENCE_BEFORE() \
    asm volatile("tcgen05.fence::before_thread_sync;" ::: "memory")
#define TCGEN05_WAIT_LD() \
    asm volatile("tcgen05.wait::ld.sync.aligned;" ::: "memory")
#define FENCE_PROXY_ASYNC_SHARED_CTA() \
    asm volatile("fence.proxy.async.shared::cta;" ::: "memory")
#define MBARRIER_INIT(mbar, count) \
    asm volatile("mbarrier.init.shared.b64 [%0], %1;" \
        :: "r"((uint32_t)(mbar)), "r"((uint32_t)(count)) : "memory")
#define MBARRIER_ARRIVE(mbar) \
    asm volatile("mbarrier.arrive.shared.b64 _, [%0];" \
        :: "r"((uint32_t)(mbar)) : "memory")
#define MBARRIER_ARRIVE_CLUSTER(local_mbar, target_rank) \
    asm volatile( \
        "{\n\t.reg .b32 remAddr32;\n\t" \
        "mapa.shared::cluster.u32 remAddr32, %0, %1;\n\t" \
        "mbarrier.arrive.shared::cluster.b64 _, [remAddr32];\n\t}" \
        :: "r"((uint32_t)(local_mbar)), "r"((uint32_t)(target_rank)) : "memory")
#define MBARRIER_WAIT_PARITY(mbar, phase_parity) do { \
    uint32_t _mbar = (uint32_t)(mbar); \
    uint32_t _parity = (uint32_t)(phase_parity); \
    uint32_t _done; \
    asm volatile( \
        "{\n\t.reg .pred p;\n\t" \
        "mbarrier.try_wait.parity.acquire.cta.shared::cta.b64 p, [%1], %2;\n\t" \
        "selp.b32 %0, 1, 0, p;\n\t}" \
        : "=r"(_done) : "r"(_mbar), "r"(_parity) : "memory"); \
    if (!_done) { \
        asm volatile( \
            "{\n\t.reg .pred P1;\n\t" \
            "WAIT_LOOP_%=:\n\t" \
            "mbarrier.try_wait.parity.acquire.cta.shared::cta.b64 P1, [%0], %1, 0x989680;\n\t" \
            "@P1 bra.uni WAIT_DONE_%=;\n\t" \
            "bra.uni WAIT_LOOP_%=;\n\t" \
            "WAIT_DONE_%=:\n\t}" \
            :: "r"(_mbar), "r"(_parity) : "memory"); \
    } \
} while(0)
#define CLUSTER_SYNC() do { \
    asm volatile("barrier.cluster.arrive.aligned;" ::: "memory"); \
    asm volatile("barrier.cluster.wait.aligned;" ::: "memory"); \
} while(0)

#define CP_ASYNC16(dst_u32, src_ptr) \
    asm volatile("cp.async.cg.shared.global [%0], [%1], 16;" \
        :: "r"(dst_u32), "l"(src_ptr) : "memory")
#define CP_COMMIT()  asm volatile("cp.async.commit_group;" ::: "memory")
#define CP_WAIT0()   asm volatile("cp.async.wait_group 0;" ::: "memory")

#define TCGEN05_LD_32X32B_X32(r, tmem_addr) \
    asm volatile( \
        "tcgen05.ld.sync.aligned.32x32b.x32.b32 " \
        "{%0, %1, %2, %3, %4, %5, %6, %7, " \
        " %8, %9, %10, %11, %12, %13, %14, %15, " \
        " %16, %17, %18, %19, %20, %21, %22, %23, " \
        " %24, %25, %26, %27, %28, %29, %30, %31}, [%32];" \
        : "=r"((r)[0]),  "=r"((r)[1]),  "=r"((r)[2]),  "=r"((r)[3]), \
          "=r"((r)[4]),  "=r"((r)[5]),  "=r"((r)[6]),  "=r"((r)[7]), \
          "=r"((r)[8]),  "=r"((r)[9]),  "=r"((r)[10]), "=r"((r)[11]), \
          "=r"((r)[12]), "=r"((r)[13]), "=r"((r)[14]), "=r"((r)[15]), \
          "=r"((r)[16]), "=r"((r)[17]), "=r"((r)[18]), "=r"((r)[19]), \
          "=r"((r)[20]), "=r"((r)[21]), "=r"((r)[22]), "=r"((r)[23]), \
          "=r"((r)[24]), "=r"((r)[25]), "=r"((r)[26]), "=r"((r)[27]), \
          "=r"((r)[28]), "=r"((r)[29]), "=r"((r)[30]), "=r"((r)[31]) \
        : "r"(tmem_addr))

// cg2 SS-mode kind::f16 MMA (bf16 in, f32 accum), M=256 across the pair.
__device__ __forceinline__ void mma_f16_ss_cg2(uint32_t d_tmem, uint64_t a_desc,
                                               uint64_t b_desc, uint32_t idesc, bool en) {
    uint32_t e = en ? 1u : 0u;
    asm volatile(
        "{\n\t.reg .pred p;\n\tsetp.ne.u32 p, %4, 0;\n\t"
        "tcgen05.mma.cta_group::2.kind::f16 [%0], %1, %2, %3, "
        "{%5, %5, %5, %5, %5, %5, %5, %5}, p;\n\t}"
        :: "r"(d_tmem), "l"(a_desc), "l"(b_desc), "r"(idesc), "r"(e), "r"(0u)
        : "memory");
}

// idesc: dtype=F32(bit4), atype=BF16(bit7), btype=BF16(bit10), N/8@[17:22], M/16@[24:28]
static constexpr uint32_t IDESC_256x256 =
    (1u << 4) | (1u << 7) | (1u << 10) | ((256u / 8u) << 17) | ((256u / 16u) << 24);
#endif  // TC_PATH

// ---------------------------------------------------------------------------
// Device scratch
// ---------------------------------------------------------------------------
__device__ int   g_idx[2][TOPK];
__device__ float g_wgt[2][TOPK];

__device__ __nv_bfloat16 g_xh[(size_t)BS * DIM_D];
__device__ __nv_bfloat16 g_xl[(size_t)BS * DIM_D];
__device__ __nv_bfloat16 g_Ab1h[(size_t)DIM_D * KR];
__device__ __nv_bfloat16 g_Ab1l[(size_t)DIM_D * KR];
__device__ __nv_bfloat16 g_Bb1th[(size_t)DIM_F * KR];
__device__ __nv_bfloat16 g_Bb1tl[(size_t)DIM_F * KR];
__device__ __nv_bfloat16 g_Ab2h[(size_t)DIM_F * KR];
__device__ __nv_bfloat16 g_Ab2l[(size_t)DIM_F * KR];
__device__ __nv_bfloat16 g_Bb2th[(size_t)DIM_D * KR];
__device__ __nv_bfloat16 g_Bb2tl[(size_t)DIM_D * KR];
__device__ __nv_bfloat16 g_W1th[(size_t)DIM_F * DIM_D];
__device__ __nv_bfloat16 g_W1tl[(size_t)DIM_F * DIM_D];
__device__ __nv_bfloat16 g_W2th[(size_t)DIM_D * DIM_F];
__device__ __nv_bfloat16 g_W2tl[(size_t)DIM_D * DIM_F];
__device__ __nv_bfloat16 g_hh[(size_t)BS * DIM_F];
__device__ __nv_bfloat16 g_hl[(size_t)BS * DIM_F];
__device__ float g_p0[(size_t)BS * DIM_D];
__device__ float g_p1[(size_t)BS * DIM_D];

__device__ __forceinline__ void split_bf16(float v, __nv_bfloat16& h, __nv_bfloat16& l) {
    h = __float2bfloat16(v);
    l = __float2bfloat16(v - __bfloat162float(h));
}

// ---------------------------------------------------------------------------
// Top-K + softmax: one warp per FC.
// ---------------------------------------------------------------------------
__global__ void topk_softmax_kernel(const float* __restrict__ logits1,
                                    const float* __restrict__ logits2) {
    const float* logits = (blockIdx.x == 0) ? logits1 : logits2;
    int which = blockIdx.x;
    int lane = threadIdx.x;
    float v[8];
    #pragma unroll
    for (int j = 0; j < 8; j++) v[j] = logits[lane * 8 + j];

    __shared__ float vals[TOPK];
    for (int k = 0; k < TOPK; k++) {
        float bv = v[0]; int bj = 0;
        #pragma unroll
        for (int j = 1; j < 8; j++) if (v[j] > bv) { bv = v[j]; bj = j; }
        int bidx = lane * 8 + bj;
        #pragma unroll
        for (int s = 16; s > 0; s >>= 1) {
            float ov = __shfl_xor_sync(0xFFFFFFFF, bv, s);
            int   oi = __shfl_xor_sync(0xFFFFFFFF, bidx, s);
            if (ov > bv || (ov == bv && oi < bidx)) { bv = ov; bidx = oi; }
        }
        if (lane == 0) { g_idx[which][k] = bidx; vals[k] = bv; }
        if (bidx >> 3 == lane) v[bidx & 7] = -3.402823466e38f;
    }
    __syncwarp();
    if (lane == 0) {
        float mx = -3.402823466e38f;
        #pragma unroll
        for (int k = 0; k < TOPK; k++) mx = fmaxf(mx, vals[k]);
        float e[TOPK]; float sum = 0.f;
        #pragma unroll
        for (int k = 0; k < TOPK; k++) { e[k] = expf(vals[k] - mx); sum += e[k]; }
        float inv = 1.f / sum;
        #pragma unroll
        for (int k = 0; k < TOPK; k++) g_wgt[which][k] = e[k] * inv;
    }
}

// ---------------------------------------------------------------------------
// Scaled A gather -> bf16 hi/lo (4 floats / thread; R3 form — measured faster)
// ---------------------------------------------------------------------------
__global__ void gather_A_kernel(const float* __restrict__ A,
                                __nv_bfloat16* __restrict__ hi,
                                __nv_bfloat16* __restrict__ lo,
                                int d_in, int which) {
    size_t total4 = (size_t)d_in * KR / 4;
    size_t vidx = (size_t)blockIdx.x * blockDim.x + threadIdx.x;
    if (vidx >= total4) return;
    size_t i = vidx * 4;
    int d = (int)(i >> 11);
    int c = (int)(i & 2047);
    int k = c >> 6;
    int r = c & 63;
    int p = g_idx[which][k];
    float w = g_wgt[which][k];
    float4 s = *reinterpret_cast<const float4*>(A + ((size_t)p * d_in + d) * DIM_R + r);
    union { __nv_bfloat16 b[4]; uint2 u; } uh, ul;
    split_bf16(w * s.x, uh.b[0], ul.b[0]);
    split_bf16(w * s.y, uh.b[1], ul.b[1]);
    split_bf16(w * s.z, uh.b[2], ul.b[2]);
    split_bf16(w * s.w, uh.b[3], ul.b[3]);
    *reinterpret_cast<uint2*>(hi + i) = uh.u;
    *reinterpret_cast<uint2*>(lo + i) = ul.u;
}

// ---------------------------------------------------------------------------
// Transposed B gather -> bf16 hi/lo (float4 loads + smem transpose)
// ---------------------------------------------------------------------------
__global__ void gather_Bt_kernel(const float* __restrict__ B,
                                 __nv_bfloat16* __restrict__ hi,
                                 __nv_bfloat16* __restrict__ lo,
                                 int d_out, int which) {
    __shared__ float tile[64][65];
    int k  = blockIdx.y;
    int f0 = blockIdx.x * 64;
    int p  = g_idx[which][k];
    int tid = threadIdx.x;
    const float* src = B + (size_t)p * DIM_R * d_out + f0;
    #pragma unroll
    for (int j = 0; j < 4; j++) {
        int id = tid + 256 * j;
        int r = id >> 4;
        int f4 = (id & 15) * 4;
        float4 v = *reinterpret_cast<const float4*>(src + (size_t)r * d_out + f4);
        tile[r][f4 + 0] = v.x; tile[r][f4 + 1] = v.y;
        tile[r][f4 + 2] = v.z; tile[r][f4 + 3] = v.w;
    }
    __syncthreads();
    int ow = tid >> 2, seg = tid & 3;
    union { __nv_bfloat16 b[8]; uint4 u; } uh0, uh1, ul0, ul1;
    #pragma unroll
    for (int e = 0; e < 16; e++) {
        float v = tile[seg * 16 + e][ow];
        __nv_bfloat16 h, l; split_bf16(v, h, l);
        if (e < 8) { uh0.b[e] = h; ul0.b[e] = l; }
        else       { uh1.b[e - 8] = h; ul1.b[e - 8] = l; }
    }
    size_t o = (size_t)(f0 + ow) * KR + (size_t)k * 64 + (size_t)seg * 16;
    *reinterpret_cast<uint4*>(hi + o)     = uh0.u;
    *reinterpret_cast<uint4*>(hi + o + 8) = uh1.u;
    *reinterpret_cast<uint4*>(lo + o)     = ul0.u;
    *reinterpret_cast<uint4*>(lo + o + 8) = ul1.u;
}

// ---------------------------------------------------------------------------
// fp32 -> bf16 hi/lo split (4 floats / thread)
// ---------------------------------------------------------------------------
__global__ void conv_split_kernel(const float* __restrict__ in,
                                  __nv_bfloat16* __restrict__ hi,
                                  __nv_bfloat16* __restrict__ lo,
                                  size_t total4) {
    size_t vidx = (size_t)blockIdx.x * blockDim.x + threadIdx.x;
    if (vidx >= total4) return;
    float4 s = reinterpret_cast<const float4*>(in)[vidx];
    union { __nv_bfloat16 b[4]; uint2 u; } uh, ul;
    split_bf16(s.x, uh.b[0], ul.b[0]);
    split_bf16(s.y, uh.b[1], ul.b[1]);
    split_bf16(s.z, uh.b[2], ul.b[2]);
    split_bf16(s.w, uh.b[3], ul.b[3]);
    reinterpret_cast<uint2*>(hi)[vidx] = uh.u;
    reinterpret_cast<uint2*>(lo)[vidx] = ul.u;
}

__global__ void add_kernel(const float* __restrict__ a, const float* __restrict__ b,
                           float* __restrict__ out, size_t total4) {
    size_t vidx = (size_t)blockIdx.x * blockDim.x + threadIdx.x;
    if (vidx >= total4) return;
    float4 x = reinterpret_cast<const float4*>(a)[vidx];
    float4 y = reinterpret_cast<const float4*>(b)[vidx];
    reinterpret_cast<float4*>(out)[vidx] =
        make_float4(x.x + y.x, x.y + y.y, x.z + y.z, x.w + y.w);
}

__device__ __forceinline__ float gelu_tanh(float x) {
    const float c0 = 0.7978845608028654f;
    const float c1 = 0.044715f;
    float x3 = x * x * x;
    return 0.5f * x * (1.0f + tanhf(c0 * (x + c1 * x3)));
}

// ---------------------------------------------------------------------------
// cg2 GEMM body: cluster of 2 CTAs computes D(256, 256) tile of
// (Ahi+Alo)(M,Ks) @ [(Bhi+Blo)(N,Ks)]^T over K range [Koff, Koff+Klen).
// CTA rank r: loads A rows [m0c + r*128, +128), B rows [n0 + r*128, +128).
// EPI: 0 fp32, 1 bf16 hi/lo, 2 gelu + bf16 hi/lo.
// ---------------------------------------------------------------------------
// Per-CTA stage: Ahi 16K | Alo 16K | Bhi 16K | Blo 16K = 64KB; two stages.
#define STAGE_BYTES 65536
#define OFF_TILES   1024
#define GEMM_SMEM   (OFF_TILES + 2 * STAGE_BYTES)   // 132096
// smem ctrl offsets
#define OFF_TMEMPTR 0
#define OFF_DONE0   8
#define OFF_DONE1   16
#define OFF_READY0  24
#define OFF_READY1  32

template <int EPI>
__device__ __forceinline__ void gemm_body_cg2(
    const __nv_bfloat16* __restrict__ Ahi, const __nv_bfloat16* __restrict__ Alo,
    const __nv_bfloat16* __restrict__ Bhi, const __nv_bfloat16* __restrict__ Blo,
    int Kstride, int Koff, int Klen, int N_total,
    float* __restrict__ outF, __nv_bfloat16* __restrict__ outHi,
    __nv_bfloat16* __restrict__ outLo, int m0c, int n0, char* smem) {
    int tid = threadIdx.x;
    uint32_t rank = cluster_rank();
#if TC_PATH
    uint32_t sb = smem_to_u32(smem);
    int wid = tid >> 5;
    int lid = tid & 31;

    if (wid == 0) TCGEN05_ALLOC_CG2(sb + OFF_TMEMPTR, 256);
    if (tid == 0) {
        MBARRIER_INIT(sb + OFF_DONE0, 1);
        MBARRIER_INIT(sb + OFF_DONE1, 1);
        MBARRIER_INIT(sb + OFF_READY0, 2);
        MBARRIER_INIT(sb + OFF_READY1, 2);
    }
    __syncthreads();
    CLUSTER_SYNC();   // peer mbarriers initialized before any remote arrive/commit
    uint32_t tmem;
    asm volatile("ld.shared.b32 %0, [%1];" : "=r"(tmem) : "r"(sb + OFF_TMEMPTR));

    int NC = Klen >> 6;
    int phd0 = 0, phd1 = 0;

    #pragma unroll 1
    for (int s = 0; s < NC; s++) {
        int st = s & 1;
        uint32_t doneb = sb + (st ? OFF_DONE1 : OFF_DONE0);
        uint32_t readyb = sb + (st ? OFF_READY1 : OFF_READY0);
        if (s >= 2) {
            if (st == 0) { MBARRIER_WAIT_PARITY(doneb, phd0 & 1); phd0++; }
            else         { MBARRIER_WAIT_PARITY(doneb, phd1 & 1); phd1++; }
        }
        int k0 = Koff + (s << 6);
        uint32_t stage = sb + OFF_TILES + st * STAGE_BYTES;
        // A rows (own 128): hi @ +0, lo @ +16384
        #pragma unroll
        for (int i = 0; i < 4; i++) {
            int cid = tid + 256 * i;
            int row = cid >> 3, c16 = cid & 7;
            size_t go = ((size_t)(m0c + rank * 128 + row) * Kstride + k0) * 2 + c16 * 16;
            uint32_t sw = SMEM_SWIZZLE_128B((uint32_t)(row * 128 + c16 * 16));
            CP_ASYNC16(stage + sw,         (const char*)Ahi + go);
            CP_ASYNC16(stage + 16384 + sw, (const char*)Alo + go);
        }
        // B rows (own half of N=256): hi @ +32768, lo @ +49152
        #pragma unroll
        for (int i = 0; i < 4; i++) {
            int cid = tid + 256 * i;
            int row = cid >> 3, c16 = cid & 7;
            size_t go = ((size_t)(n0 + rank * 128 + row) * Kstride + k0) * 2 + c16 * 16;
            uint32_t sw = SMEM_SWIZZLE_128B((uint32_t)(row * 128 + c16 * 16));
            CP_ASYNC16(stage + 32768 + sw, (const char*)Bhi + go);
            CP_ASYNC16(stage + 49152 + sw, (const char*)Blo + go);
        }
        CP_COMMIT();
        CP_WAIT0();
        FENCE_PROXY_ASYNC_SHARED_CTA();
        __syncthreads();

        if (wid == 0 && elect_one_pred()) {
            if (rank == 0) {
                MBARRIER_ARRIVE(readyb);
                MBARRIER_WAIT_PARITY(readyb, (s >> 1) & 1);
                uint64_t dAh = MAKE_SMEM_DESC(stage);
                uint64_t dAl = MAKE_SMEM_DESC(stage + 16384);
                uint64_t dBh = MAKE_SMEM_DESC(stage + 32768);
                uint64_t dBl = MAKE_SMEM_DESC(stage + 49152);
                #pragma unroll
                for (int c = 0; c < 3; c++) {
                    uint64_t dA = (c == 2) ? dAl : dAh;
                    uint64_t dB = (c == 1) ? dBl : dBh;
                    #pragma unroll
                    for (int ks = 0; ks < 4; ks++) {
                        bool en = !(s == 0 && c == 0 && ks == 0);
                        mma_f16_ss_cg2(tmem, dA + ks * 2, dB + ks * 2,
                                       IDESC_256x256, en);
                    }
                }
                TCGEN05_COMMIT_MULTICAST_CG2(doneb, 0x3);
            } else {
                MBARRIER_ARRIVE_CLUSTER(readyb, 0);
            }
        }
    }

    MBARRIER_WAIT_PARITY(sb + OFF_DONE0, phd0 & 1);
    MBARRIER_WAIT_PARITY(sb + OFF_DONE1, phd1 & 1);
    TCGEN05_FENCE_AFTER();

    if (wid < 4) {
        int row = m0c + rank * 128 + wid * 32 + lid;
        #pragma unroll 1
        for (int nb = 0; nb < 8; nb++) {
            uint32_t r[32];
            TCGEN05_LD_32X32B_X32(r, tmem + nb * 32);
            TCGEN05_WAIT_LD();
            int nc0 = n0 + nb * 32;
            if (EPI == 0) {
                #pragma unroll
                for (int j = 0; j < 8; j++) {
                    float4 o = make_float4(__uint_as_float(r[4 * j + 0]),
                                           __uint_as_float(r[4 * j + 1]),
                                           __uint_as_float(r[4 * j + 2]),
                                           __uint_as_float(r[4 * j + 3]));
                    *reinterpret_cast<float4*>(outF + (size_t)row * N_total + nc0 + 4 * j) = o;
                }
            } else {
                #pragma unroll
                for (int j = 0; j < 4; j++) {
                    union { __nv_bfloat16 b[8]; uint4 u; } uh, ul;
                    #pragma unroll
                    for (int e = 0; e < 8; e++) {
                        float v = __uint_as_float(r[8 * j + e]);
                        if (EPI == 2) v = gelu_tanh(v);
                        split_bf16(v, uh.b[e], ul.b[e]);
                    }
                    size_t o = (size_t)row * N_total + nc0 + 8 * j;
                    *reinterpret_cast<uint4*>(outHi + o) = uh.u;
                    *reinterpret_cast<uint4*>(outLo + o) = ul.u;
                }
            }
        }
        TCGEN05_FENCE_BEFORE();
    }

    __syncthreads();
    if (wid == 0) {
        TCGEN05_RELINQUISH_CG2();
        TCGEN05_DEALLOC_CG2(tmem, 256);
    }
    CLUSTER_SYNC();   // no CTA exits while peer MMA/commit may touch its SMEM
#else
    // ---------------- FFMA fallback: each CTA computes its 128x256 half ----
    int m0 = m0c + (int)rank * 128;
    float* As = reinterpret_cast<float*>(smem);             // [16][132]
    float* Bs = reinterpret_cast<float*>(smem) + 16 * 132;  // [16][68]
    int tx = tid & 15;
    int ty = tid >> 4;

    #pragma unroll 1
    for (int nchunk = 0; nchunk < 4; nchunk++) {
        int nbase = n0 + nchunk * 64;
        float acc[8][4];
        #pragma unroll
        for (int i = 0; i < 8; i++)
            #pragma unroll
            for (int j = 0; j < 4; j++) acc[i][j] = 0.f;

        #pragma unroll 1
        for (int k0 = Koff; k0 < Koff + Klen; k0 += 16) {
            {
                int row = tid >> 1;
                int kseg = (tid & 1) * 8;
                size_t go = (size_t)(m0 + row) * Kstride + k0 + kseg;
                union { uint4 u; __nv_bfloat16 b[8]; } vh, vl;
                vh.u = *reinterpret_cast<const uint4*>(Ahi + go);
                vl.u = *reinterpret_cast<const uint4*>(Alo + go);
                #pragma unroll
                for (int e = 0; e < 8; e++)
                    As[(kseg + e) * 132 + row] =
                        __bfloat162float(vh.b[e]) + __bfloat162float(vl.b[e]);
            }
            {
                int row = tid >> 2;
                int kseg = (tid & 3) * 4;
                size_t go = (size_t)(nbase + row) * Kstride + k0 + kseg;
                union { uint2 u; __nv_bfloat16 b[4]; } vh, vl;
                vh.u = *reinterpret_cast<const uint2*>(Bhi + go);
                vl.u = *reinterpret_cast<const uint2*>(Blo + go);
                #pragma unroll
                for (int e = 0; e < 4; e++)
                    Bs[(kseg + e) * 68 + row] =
                        __bfloat162float(vh.b[e]) + __bfloat162float(vl.b[e]);
            }
            __syncthreads();
            #pragma unroll
            for (int kk = 0; kk < 16; kk++) {
                float a0[8], b0[4];
                float4 a4a = *reinterpret_cast<const float4*>(&As[kk * 132 + ty * 8]);
                float4 a4b = *reinterpret_cast<const float4*>(&As[kk * 132 + ty * 8 + 4]);
                float4 b4  = *reinterpret_cast<const float4*>(&Bs[kk * 68 + tx * 4]);
                a0[0]=a4a.x; a0[1]=a4a.y; a0[2]=a4a.z; a0[3]=a4a.w;
                a0[4]=a4b.x; a0[5]=a4b.y; a0[6]=a4b.z; a0[7]=a4b.w;
                b0[0]=b4.x;  b0[1]=b4.y;  b0[2]=b4.z;  b0[3]=b4.w;
                #pragma unroll
                for (int i = 0; i < 8; i++)
                    #pragma unroll
                    for (int j = 0; j < 4; j++)
                        acc[i][j] = fmaf(a0[i], b0[j], acc[i][j]);
            }
            __syncthreads();
        }

        #pragma unroll
        for (int i = 0; i < 8; i++) {
            int row = m0 + ty * 8 + i;
            int col = nbase + tx * 4;
            if (EPI == 0) {
                float4 o = make_float4(acc[i][0], acc[i][1], acc[i][2], acc[i][3]);
                *reinterpret_cast<float4*>(outF + (size_t)row * N_total + col) = o;
            } else {
                union { __nv_bfloat16 b[4]; uint2 u; } uh, ul;
                #pragma unroll
                for (int j = 0; j < 4; j++) {
                    float v = acc[i][j];
                    if (EPI == 2) v = gelu_tanh(v);
                    split_bf16(v, uh.b[j], ul.b[j]);
                }
                size_t o = (size_t)row * N_total + col;
                *reinterpret_cast<uint2*>(outHi + o) = uh.u;
                *reinterpret_cast<uint2*>(outLo + o) = ul.u;
            }
        }
    }
#endif
}

// ---------------------------------------------------------------------------
// GEMM wrappers (all cluster (2,1,1); grid.x counts CTAs = 2 * n-clusters)
// ---------------------------------------------------------------------------
// Fused compose: cid < 64 -> W1t (M=4096, N=1024); else W2t (M=1024, N=4096)
__global__ void __launch_bounds__(256, 1) __cluster_dims__(2, 1, 1)
compose_fused_kernel(const __nv_bfloat16* A1h, const __nv_bfloat16* A1l,
                     const __nv_bfloat16* B1h, const __nv_bfloat16* B1l,
                     __nv_bfloat16* o1h, __nv_bfloat16* o1l,
                     const __nv_bfloat16* A2h, const __nv_bfloat16* A2l,
                     const __nv_bfloat16* B2h, const __nv_bfloat16* B2l,
                     __nv_bfloat16* o2h, __nv_bfloat16* o2l) {
    extern __shared__ __align__(1024) char smem[];
    int cid = blockIdx.x >> 1;
    if (cid < 64) {
        int m0c = (cid >> 2) * 256;    // 16 m-clusters (M=4096)
        int n0  = (cid & 3) * 256;     // 4 n-tiles (N=1024)
        gemm_body_cg2<1>(A1h, A1l, B1h, B1l, KR, 0, KR, DIM_D,
                         nullptr, o1h, o1l, m0c, n0, smem);
    } else {
        cid -= 64;
        int m0c = (cid >> 4) * 256;    // 4 m-clusters (M=1024)
        int n0  = (cid & 15) * 256;    // 16 n-tiles (N=4096)
        gemm_body_cg2<1>(A2h, A2l, B2h, B2l, KR, 0, KR, DIM_F,
                         nullptr, o2h, o2l, m0c, n0, smem);
    }
}

template <int EPI>
__global__ void __launch_bounds__(256, 1) __cluster_dims__(2, 1, 1)
gemm_kernel(const __nv_bfloat16* Ahi, const __nv_bfloat16* Alo,
            const __nv_bfloat16* Bhi, const __nv_bfloat16* Blo,
            int Kstride, int Koff, int Klen, int N_total,
            float* outF, __nv_bfloat16* outHi, __nv_bfloat16* outLo) {
    extern __shared__ __align__(1024) char smem[];
    gemm_body_cg2<EPI>(Ahi, Alo, Bhi, Blo, Kstride, Koff, Klen, N_total,
                       outF, outHi, outLo, blockIdx.y * 256,
                       (blockIdx.x >> 1) * 256, smem);
}

__global__ void __launch_bounds__(256, 1) __cluster_dims__(2, 1, 1)
gemm_splitk_kernel(const __nv_bfloat16* Ahi, const __nv_bfloat16* Alo,
                   const __nv_bfloat16* Bhi, const __nv_bfloat16* Blo,
                   int Kstride, int N_total, float* p0, float* p1) {
    extern __shared__ __align__(1024) char smem[];
    int z = blockIdx.z;
    gemm_body_cg2<0>(Ahi, Alo, Bhi, Blo, Kstride, z * (Kstride / 2), Kstride / 2,
                     N_total, z ? p1 : p0, nullptr, nullptr,
                     blockIdx.y * 256, (blockIdx.x >> 1) * 256, smem);
}

// ---------------------------------------------------------------------------
// Launch
// ---------------------------------------------------------------------------
extern "C" void kernel_launch(void* const* d_in, const int* in_sizes, int n_in,
                              void* d_out, int out_size) {
    const float* x     = (const float*)d_in[0];
    const float* fc1_A = (const float*)d_in[1];
    const float* fc1_B = (const float*)d_in[2];
    const float* fc2_A = (const float*)d_in[3];
    const float* fc2_B = (const float*)d_in[4];
    const float* l1    = (const float*)d_in[5];
    const float* l2    = (const float*)d_in[6];
    float* out = (float*)d_out;

    __nv_bfloat16 *xh, *xl, *Ab1h, *Ab1l, *Bb1th, *Bb1tl, *Ab2h, *Ab2l,
                  *Bb2th, *Bb2tl, *W1th, *W1tl, *W2th, *W2tl, *hh, *hl;
    float *p0, *p1;
    cudaGetSymbolAddress((void**)&xh, g_xh);     cudaGetSymbolAddress((void**)&xl, g_xl);
    cudaGetSymbolAddress((void**)&Ab1h, g_Ab1h); cudaGetSymbolAddress((void**)&Ab1l, g_Ab1l);
    cudaGetSymbolAddress((void**)&Bb1th, g_Bb1th); cudaGetSymbolAddress((void**)&Bb1tl, g_Bb1tl);
    cudaGetSymbolAddress((void**)&Ab2h, g_Ab2h); cudaGetSymbolAddress((void**)&Ab2l, g_Ab2l);
    cudaGetSymbolAddress((void**)&Bb2th, g_Bb2th); cudaGetSymbolAddress((void**)&Bb2tl, g_Bb2tl);
    cudaGetSymbolAddress((void**)&W1th, g_W1th); cudaGetSymbolAddress((void**)&W1tl, g_W1tl);
    cudaGetSymbolAddress((void**)&W2th, g_W2th); cudaGetSymbolAddress((void**)&W2tl, g_W2tl);
    cudaGetSymbolAddress((void**)&hh, g_hh);     cudaGetSymbolAddress((void**)&hl, g_hl);
    cudaGetSymbolAddress((void**)&p0, g_p0);     cudaGetSymbolAddress((void**)&p1, g_p1);

    cudaFuncSetAttribute(compose_fused_kernel, cudaFuncAttributeMaxDynamicSharedMemorySize, GEMM_SMEM);
    cudaFuncSetAttribute(gemm_kernel<2>, cudaFuncAttributeMaxDynamicSharedMemorySize, GEMM_SMEM);
    cudaFuncSetAttribute(gemm_splitk_kernel, cudaFuncAttributeMaxDynamicSharedMemorySize, GEMM_SMEM);

    topk_softmax_kernel<<<2, 32>>>(l1, l2);

    {
        size_t n4;
        n4 = (size_t)BS * DIM_D / 4;
        conv_split_kernel<<<(unsigned)((n4 + 255) / 256), 256>>>(x, xh, xl, n4);
        n4 = (size_t)DIM_D * KR / 4;
        gather_A_kernel<<<(unsigned)((n4 + 255) / 256), 256>>>(fc1_A, Ab1h, Ab1l, DIM_D, 0);
        n4 = (size_t)DIM_F * KR / 4;
        gather_A_kernel<<<(unsigned)((n4 + 255) / 256), 256>>>(fc2_A, Ab2h, Ab2l, DIM_F, 1);
        gather_Bt_kernel<<<dim3(DIM_F / 64, TOPK), 256>>>(fc1_B, Bb1th, Bb1tl, DIM_F, 0);
        gather_Bt_kernel<<<dim3(DIM_D / 64, TOPK), 256>>>(fc2_B, Bb2th, Bb2tl, DIM_D, 1);
    }

    // Fused compose: W1t (F x D) and W2t (D x F); 128 clusters = 256 CTAs
    compose_fused_kernel<<<256, 256, GEMM_SMEM>>>(
        Bb1th, Bb1tl, Ab1h, Ab1l, W1th, W1tl,
        Bb2th, Bb2tl, Ab2h, Ab2l, W2th, W2tl);

    // h (BS x F) = gelu( x @ W1t^T ): 8 m-clusters x 16 n-tiles
    gemm_kernel<2><<<dim3(DIM_F / 256 * 2, BS / 256), 256, GEMM_SMEM>>>(
        xh, xl, W1th, W1tl, DIM_D, 0, DIM_D, DIM_F, nullptr, hh, hl);

    // out (BS x D) = h @ W2t^T  — split-K x2 + add
    gemm_splitk_kernel<<<dim3(DIM_D / 256 * 2, BS / 256, 2), 256, GEMM_SMEM>>>(
        hh, hl, W2th, W2tl, DIM_F, DIM_D, p0, p1);
    add_kernel<<<(BS * DIM_D / 4 + 255) / 256, 256>>>(p0, p1, out, (size_t)BS * DIM_D / 4);
}

// round 6
// speedup vs baseline: 9.5684x; 1.1606x over previous
#include <cuda_runtime.h>
#include <cuda_bf16.h>
#include <math.h>
#include <stdint.h>

// ---------------------------------------------------------------------------
// Problem constants: B=2, S=1024, D=1024, F=4096, P=256, R=64, K=32.
// ---------------------------------------------------------------------------
#define DIM_D 1024
#define DIM_F 4096
#define DIM_P 256
#define DIM_R 64
#define TOPK  32
#define BS    2048
#define KR    (TOPK * DIM_R)   // 2048

// ---------------------------------------------------------------------------
// Feature detection: tcgen05 only on sm_103a target; plain compute_103 pass
// gets an FFMA fallback with identical semantics.
// ---------------------------------------------------------------------------
#if defined(__CUDA_ARCH__)
#  ifdef __CUDA_ARCH_HAS_FEATURE__
#    if __CUDA_ARCH_HAS_FEATURE__(SM103_ALL)
#      define TC_PATH 1
#    endif
#  endif
#  ifndef TC_PATH
#    ifdef __CUDA_ARCH_FEAT_SM103_ALL
#      define TC_PATH 1
#    else
#      define TC_PATH 0
#    endif
#  endif
#else
#  define TC_PATH 0
#endif

// ---------------------------------------------------------------------------
// PTX helpers
// ---------------------------------------------------------------------------
__device__ __forceinline__ uint32_t smem_to_u32(const void* smem_ptr) {
    uint32_t addr;
    asm("{ .reg .u64 tmp; cvta.to.shared.u64 tmp, %1; cvt.u32.u64 %0, tmp; }"
        : "=r"(addr) : "l"(smem_ptr));
    return addr;
}
#define SMEM_SWIZZLE_128B(byte_offset) \
    ((byte_offset) ^ (((byte_offset) >> 3) & 0x70))

__device__ __forceinline__ uint32_t cluster_rank() {
    uint32_t r;
    asm("mov.u32 %0, %%cluster_ctarank;" : "=r"(r));
    return r;
}

#if TC_PATH
__device__ __forceinline__ uint32_t elect_one_pred() {
    uint32_t pred;
    asm volatile(
        "{\n\t.reg .pred p;\n\telect.sync _|p, 0xFFFFFFFF;\n\tselp.b32 %0, 1, 0, p;\n\t}"
        : "=r"(pred));
    return pred;
}

static constexpr uint64_t SMEM_DESC_BASE_SW128 =
    (uint64_t(2)  << 61) | (uint64_t(1) << 46) | (uint64_t(64) << 32) | (uint64_t(1) << 16);
#define MAKE_SMEM_DESC(base_addr) \
    (SMEM_DESC_BASE_SW128 | ((uint64_t)((base_addr) >> 4) & 0x3FFF))

#define TCGEN05_ALLOC_CG2(smem_result_addr, nCols) \
    asm volatile("tcgen05.alloc.cta_group::2.sync.aligned.shared::cta.b32 [%0], %1;" \
        :: "r"((uint32_t)(smem_result_addr)), "r"((uint32_t)(nCols)) : "memory")
#define TCGEN05_DEALLOC_CG2(tmem_addr, nCols) \
    asm volatile("tcgen05.dealloc.cta_group::2.sync.aligned.b32 %0, %1;" \
        :: "r"(tmem_addr), "r"((uint32_t)(nCols)))
#define TCGEN05_RELINQUISH_CG2() \
    asm volatile("tcgen05.relinquish_alloc_permit.cta_group::2.sync.aligned;")
#define TCGEN05_COMMIT_MULTICAST_CG2(mbar, mask) \
    asm volatile("tcgen05.commit.cta_group::2.mbarrier::arrive::one.shared::cluster.multicast::cluster.b64 [%0], %1;" \
        :: "r"((uint32_t)(mbar)), "h"((uint16_t)(mask)) : "memory")
#define TCGEN05_FENCE_AFTER() \
    asm volatile("tcgen05.fence::after_thread_sync;" ::: "memory")
#define TCGEN05_FENCE_BEFORE() \
    asm volatile("tcgen05.fence::before_thread_sync;" ::: "memory")
#define TCGEN05_WAIT_LD() \
    asm volatile("tcgen05.wait::ld.sync.aligned;" ::: "memory")
#define FENCE_PROXY_ASYNC_SHARED_CTA() \
    asm volatile("fence.proxy.async.shared::cta;" ::: "memory")
#define MBARRIER_INIT(mbar, count) \
    asm volatile("mbarrier.init.shared.b64 [%0], %1;" \
        :: "r"((uint32_t)(mbar)), "r"((uint32_t)(count)) : "memory")
#define MBARRIER_ARRIVE(mbar) \
    asm volatile("mbarrier.arrive.shared.b64 _, [%0];" \
        :: "r"((uint32_t)(mbar)) : "memory")
#define MBARRIER_ARRIVE_CLUSTER(local_mbar, target_rank) \
    asm volatile( \
        "{\n\t.reg .b32 remAddr32;\n\t" \
        "mapa.shared::cluster.u32 remAddr32, %0, %1;\n\t" \
        "mbarrier.arrive.shared::cluster.b64 _, [remAddr32];\n\t}" \
        :: "r"((uint32_t)(local_mbar)), "r"((uint32_t)(target_rank)) : "memory")
#define MBARRIER_WAIT_PARITY(mbar, phase_parity) do { \
    uint32_t _mbar = (uint32_t)(mbar); \
    uint32_t _parity = (uint32_t)(phase_parity); \
    uint32_t _done; \
    asm volatile( \
        "{\n\t.reg .pred p;\n\t" \
        "mbarrier.try_wait.parity.acquire.cta.shared::cta.b64 p, [%1], %2;\n\t" \
        "selp.b32 %0, 1, 0, p;\n\t}" \
        : "=r"(_done) : "r"(_mbar), "r"(_parity) : "memory"); \
    if (!_done) { \
        asm volatile( \
            "{\n\t.reg .pred P1;\n\t" \
            "WAIT_LOOP_%=:\n\t" \
            "mbarrier.try_wait.parity.acquire.cta.shared::cta.b64 P1, [%0], %1, 0x989680;\n\t" \
            "@P1 bra.uni WAIT_DONE_%=;\n\t" \
            "bra.uni WAIT_LOOP_%=;\n\t" \
            "WAIT_DONE_%=:\n\t}" \
            :: "r"(_mbar), "r"(_parity) : "memory"); \
    } \
} while(0)
#define CLUSTER_SYNC() do { \
    asm volatile("barrier.cluster.arrive.aligned;" ::: "memory"); \
    asm volatile("barrier.cluster.wait.aligned;" ::: "memory"); \
} while(0)

#define CP_ASYNC16(dst_u32, src_ptr) \
    asm volatile("cp.async.cg.shared.global [%0], [%1], 16;" \
        :: "r"(dst_u32), "l"(src_ptr) : "memory")
#define CP_COMMIT()  asm volatile("cp.async.commit_group;" ::: "memory")
#define CP_WAIT0()   asm volatile("cp.async.wait_group 0;" ::: "memory")
#define CP_WAIT1()   asm volatile("cp.async.wait_group 1;" ::: "memory")

#define TCGEN05_LD_32X32B_X32(r, tmem_addr) \
    asm volatile( \
        "tcgen05.ld.sync.aligned.32x32b.x32.b32 " \
        "{%0, %1, %2, %3, %4, %5, %6, %7, " \
        " %8, %9, %10, %11, %12, %13, %14, %15, " \
        " %16, %17, %18, %19, %20, %21, %22, %23, " \
        " %24, %25, %26, %27, %28, %29, %30, %31}, [%32];" \
        : "=r"((r)[0]),  "=r"((r)[1]),  "=r"((r)[2]),  "=r"((r)[3]), \
          "=r"((r)[4]),  "=r"((r)[5]),  "=r"((r)[6]),  "=r"((r)[7]), \
          "=r"((r)[8]),  "=r"((r)[9]),  "=r"((r)[10]), "=r"((r)[11]), \
          "=r"((r)[12]), "=r"((r)[13]), "=r"((r)[14]), "=r"((r)[15]), \
          "=r"((r)[16]), "=r"((r)[17]), "=r"((r)[18]), "=r"((r)[19]), \
          "=r"((r)[20]), "=r"((r)[21]), "=r"((r)[22]), "=r"((r)[23]), \
          "=r"((r)[24]), "=r"((r)[25]), "=r"((r)[26]), "=r"((r)[27]), \
          "=r"((r)[28]), "=r"((r)[29]), "=r"((r)[30]), "=r"((r)[31]) \
        : "r"(tmem_addr))

// cg2 SS-mode kind::f16 MMA (bf16 in, f32 accum), M=256 across the pair.
__device__ __forceinline__ void mma_f16_ss_cg2(uint32_t d_tmem, uint64_t a_desc,
                                               uint64_t b_desc, uint32_t idesc, bool en) {
    uint32_t e = en ? 1u : 0u;
    asm volatile(
        "{\n\t.reg .pred p;\n\tsetp.ne.u32 p, %4, 0;\n\t"
        "tcgen05.mma.cta_group::2.kind::f16 [%0], %1, %2, %3, "
        "{%5, %5, %5, %5, %5, %5, %5, %5}, p;\n\t}"
        :: "r"(d_tmem), "l"(a_desc), "l"(b_desc), "r"(idesc), "r"(e), "r"(0u)
        : "memory");
}

// idesc: dtype=F32(bit4), atype=BF16(bit7), btype=BF16(bit10), N/8@[17:22], M/16@[24:28]
static constexpr uint32_t IDESC_256x256 =
    (1u << 4) | (1u << 7) | (1u << 10) | ((256u / 8u) << 17) | ((256u / 16u) << 24);
#endif  // TC_PATH

// ---------------------------------------------------------------------------
// Device scratch
// ---------------------------------------------------------------------------
__device__ int   g_idx[2][TOPK];
__device__ float g_wgt[2][TOPK];

__device__ __nv_bfloat16 g_xh[(size_t)BS * DIM_D];
__device__ __nv_bfloat16 g_xl[(size_t)BS * DIM_D];
__device__ __nv_bfloat16 g_Ab1h[(size_t)DIM_D * KR];
__device__ __nv_bfloat16 g_Ab1l[(size_t)DIM_D * KR];
__device__ __nv_bfloat16 g_Bb1th[(size_t)DIM_F * KR];
__device__ __nv_bfloat16 g_Bb1tl[(size_t)DIM_F * KR];
__device__ __nv_bfloat16 g_Ab2h[(size_t)DIM_F * KR];
__device__ __nv_bfloat16 g_Ab2l[(size_t)DIM_F * KR];
__device__ __nv_bfloat16 g_Bb2th[(size_t)DIM_D * KR];
__device__ __nv_bfloat16 g_Bb2tl[(size_t)DIM_D * KR];
__device__ __nv_bfloat16 g_W1th[(size_t)DIM_F * DIM_D];
__device__ __nv_bfloat16 g_W1tl[(size_t)DIM_F * DIM_D];
__device__ __nv_bfloat16 g_W2th[(size_t)DIM_D * DIM_F];
__device__ __nv_bfloat16 g_W2tl[(size_t)DIM_D * DIM_F];
__device__ __nv_bfloat16 g_hh[(size_t)BS * DIM_F];
__device__ __nv_bfloat16 g_hl[(size_t)BS * DIM_F];
__device__ float g_p0[(size_t)BS * DIM_D];
__device__ float g_p1[(size_t)BS * DIM_D];

__device__ __forceinline__ void split_bf16(float v, __nv_bfloat16& h, __nv_bfloat16& l) {
    h = __float2bfloat16(v);
    l = __float2bfloat16(v - __bfloat162float(h));
}

// ---------------------------------------------------------------------------
// Top-K + softmax: one warp per FC.
// ---------------------------------------------------------------------------
__global__ void topk_softmax_kernel(const float* __restrict__ logits1,
                                    const float* __restrict__ logits2) {
    const float* logits = (blockIdx.x == 0) ? logits1 : logits2;
    int which = blockIdx.x;
    int lane = threadIdx.x;
    float v[8];
    #pragma unroll
    for (int j = 0; j < 8; j++) v[j] = logits[lane * 8 + j];

    __shared__ float vals[TOPK];
    for (int k = 0; k < TOPK; k++) {
        float bv = v[0]; int bj = 0;
        #pragma unroll
        for (int j = 1; j < 8; j++) if (v[j] > bv) { bv = v[j]; bj = j; }
        int bidx = lane * 8 + bj;
        #pragma unroll
        for (int s = 16; s > 0; s >>= 1) {
            float ov = __shfl_xor_sync(0xFFFFFFFF, bv, s);
            int   oi = __shfl_xor_sync(0xFFFFFFFF, bidx, s);
            if (ov > bv || (ov == bv && oi < bidx)) { bv = ov; bidx = oi; }
        }
        if (lane == 0) { g_idx[which][k] = bidx; vals[k] = bv; }
        if (bidx >> 3 == lane) v[bidx & 7] = -3.402823466e38f;
    }
    __syncwarp();
    if (lane == 0) {
        float mx = -3.402823466e38f;
        #pragma unroll
        for (int k = 0; k < TOPK; k++) mx = fmaxf(mx, vals[k]);
        float e[TOPK]; float sum = 0.f;
        #pragma unroll
        for (int k = 0; k < TOPK; k++) { e[k] = expf(vals[k] - mx); sum += e[k]; }
        float inv = 1.f / sum;
        #pragma unroll
        for (int k = 0; k < TOPK; k++) g_wgt[which][k] = e[k] * inv;
    }
}

// ---------------------------------------------------------------------------
// Scaled A gather -> bf16 hi/lo. 8 elems/thread: 2x LDG.128, 2x STG.128.
// ---------------------------------------------------------------------------
__global__ void gather_A_kernel(const float* __restrict__ A,
                                __nv_bfloat16* __restrict__ hi,
                                __nv_bfloat16* __restrict__ lo,
                                int d_in, int which) {
    size_t vidx = (size_t)blockIdx.x * blockDim.x + threadIdx.x;
    size_t i = vidx * 8;
    if (i >= (size_t)d_in * KR) return;
    int d = (int)(i >> 11);
    int c = (int)(i & 2047);
    int k = c >> 6;
    int r = c & 63;           // multiple of 8
    int p = g_idx[which][k];
    float w = g_wgt[which][k];
    const float* src = A + ((size_t)p * d_in + d) * DIM_R + r;
    float4 s0 = *reinterpret_cast<const float4*>(src);
    float4 s1 = *reinterpret_cast<const float4*>(src + 4);
    union { __nv_bfloat16 b[8]; uint4 u; } uh, ul;
    split_bf16(w * s0.x, uh.b[0], ul.b[0]);
    split_bf16(w * s0.y, uh.b[1], ul.b[1]);
    split_bf16(w * s0.z, uh.b[2], ul.b[2]);
    split_bf16(w * s0.w, uh.b[3], ul.b[3]);
    split_bf16(w * s1.x, uh.b[4], ul.b[4]);
    split_bf16(w * s1.y, uh.b[5], ul.b[5]);
    split_bf16(w * s1.z, uh.b[6], ul.b[6]);
    split_bf16(w * s1.w, uh.b[7], ul.b[7]);
    *reinterpret_cast<uint4*>(hi + i) = uh.u;
    *reinterpret_cast<uint4*>(lo + i) = ul.u;
}

// ---------------------------------------------------------------------------
// Transposed B gather -> bf16 hi/lo (float4 loads + smem transpose)
// ---------------------------------------------------------------------------
__global__ void gather_Bt_kernel(const float* __restrict__ B,
                                 __nv_bfloat16* __restrict__ hi,
                                 __nv_bfloat16* __restrict__ lo,
                                 int d_out, int which) {
    __shared__ float tile[64][65];
    int k  = blockIdx.y;
    int f0 = blockIdx.x * 64;
    int p  = g_idx[which][k];
    int tid = threadIdx.x;
    const float* src = B + (size_t)p * DIM_R * d_out + f0;
    #pragma unroll
    for (int j = 0; j < 4; j++) {
        int id = tid + 256 * j;
        int r = id >> 4;
        int f4 = (id & 15) * 4;
        float4 v = *reinterpret_cast<const float4*>(src + (size_t)r * d_out + f4);
        tile[r][f4 + 0] = v.x; tile[r][f4 + 1] = v.y;
        tile[r][f4 + 2] = v.z; tile[r][f4 + 3] = v.w;
    }
    __syncthreads();
    int ow = tid >> 2, seg = tid & 3;
    union { __nv_bfloat16 b[8]; uint4 u; } uh0, uh1, ul0, ul1;
    #pragma unroll
    for (int e = 0; e < 16; e++) {
        float v = tile[seg * 16 + e][ow];
        __nv_bfloat16 h, l; split_bf16(v, h, l);
        if (e < 8) { uh0.b[e] = h; ul0.b[e] = l; }
        else       { uh1.b[e - 8] = h; ul1.b[e - 8] = l; }
    }
    size_t o = (size_t)(f0 + ow) * KR + (size_t)k * 64 + (size_t)seg * 16;
    *reinterpret_cast<uint4*>(hi + o)     = uh0.u;
    *reinterpret_cast<uint4*>(hi + o + 8) = uh1.u;
    *reinterpret_cast<uint4*>(lo + o)     = ul0.u;
    *reinterpret_cast<uint4*>(lo + o + 8) = ul1.u;
}

// ---------------------------------------------------------------------------
// fp32 -> bf16 hi/lo split, 8 elems/thread
// ---------------------------------------------------------------------------
__global__ void conv_split_kernel(const float* __restrict__ in,
                                  __nv_bfloat16* __restrict__ hi,
                                  __nv_bfloat16* __restrict__ lo,
                                  size_t total) {
    size_t i = ((size_t)blockIdx.x * blockDim.x + threadIdx.x) * 8;
    if (i >= total) return;
    float4 s0 = *reinterpret_cast<const float4*>(in + i);
    float4 s1 = *reinterpret_cast<const float4*>(in + i + 4);
    union { __nv_bfloat16 b[8]; uint4 u; } uh, ul;
    split_bf16(s0.x, uh.b[0], ul.b[0]);
    split_bf16(s0.y, uh.b[1], ul.b[1]);
    split_bf16(s0.z, uh.b[2], ul.b[2]);
    split_bf16(s0.w, uh.b[3], ul.b[3]);
    split_bf16(s1.x, uh.b[4], ul.b[4]);
    split_bf16(s1.y, uh.b[5], ul.b[5]);
    split_bf16(s1.z, uh.b[6], ul.b[6]);
    split_bf16(s1.w, uh.b[7], ul.b[7]);
    *reinterpret_cast<uint4*>(hi + i) = uh.u;
    *reinterpret_cast<uint4*>(lo + i) = ul.u;
}

__global__ void add_kernel(const float* __restrict__ a, const float* __restrict__ b,
                           float* __restrict__ out, size_t total4) {
    size_t vidx = (size_t)blockIdx.x * blockDim.x + threadIdx.x;
    if (vidx >= total4) return;
    float4 x = reinterpret_cast<const float4*>(a)[vidx];
    float4 y = reinterpret_cast<const float4*>(b)[vidx];
    reinterpret_cast<float4*>(out)[vidx] =
        make_float4(x.x + y.x, x.y + y.y, x.z + y.z, x.w + y.w);
}

__device__ __forceinline__ float gelu_tanh(float x) {
    const float c0 = 0.7978845608028654f;
    const float c1 = 0.044715f;
    float x3 = x * x * x;
    return 0.5f * x * (1.0f + tanhf(c0 * (x + c1 * x3)));
}

// ---------------------------------------------------------------------------
// cg2 GEMM body, 3-stage cp.async pipeline.
// Cluster of 2 CTAs computes D(256,256) tile of (Ahi+Alo) @ [(Bhi+Blo)]^T.
// ---------------------------------------------------------------------------
#define STAGE_BYTES 65536
#define OFF_TILES   1024
#define NSTAGE      3
#define GEMM_SMEM   (OFF_TILES + NSTAGE * STAGE_BYTES)   // 197632
#define OFF_TMEMPTR 0
#define OFF_DONE(b)  (8 + (b) * 8)      // 3 done barriers
#define OFF_READY(b) (32 + (b) * 8)     // 3 ready barriers

template <int EPI>
__device__ __forceinline__ void gemm_body_cg2(
    const __nv_bfloat16* __restrict__ Ahi, const __nv_bfloat16* __restrict__ Alo,
    const __nv_bfloat16* __restrict__ Bhi, const __nv_bfloat16* __restrict__ Blo,
    int Kstride, int Koff, int Klen, int N_total,
    float* __restrict__ outF, __nv_bfloat16* __restrict__ outHi,
    __nv_bfloat16* __restrict__ outLo, int m0c, int n0, char* smem) {
    int tid = threadIdx.x;
    uint32_t rank = cluster_rank();
#if TC_PATH
    uint32_t sb = smem_to_u32(smem);
    int wid = tid >> 5;
    int lid = tid & 31;

    if (wid == 0) TCGEN05_ALLOC_CG2(sb + OFF_TMEMPTR, 256);
    if (tid == 0) {
        #pragma unroll
        for (int b = 0; b < NSTAGE; b++) {
            MBARRIER_INIT(sb + OFF_DONE(b), 1);
            MBARRIER_INIT(sb + OFF_READY(b), 2);
        }
    }
    __syncthreads();
    CLUSTER_SYNC();
    uint32_t tmem;
    asm volatile("ld.shared.b32 %0, [%1];" : "=r"(tmem) : "r"(sb + OFF_TMEMPTR));

    int NC = Klen >> 6;

    auto load_stage = [&](int ss) {
        int k0 = Koff + (ss << 6);
        uint32_t stage = sb + OFF_TILES + (uint32_t)(ss % NSTAGE) * STAGE_BYTES;
        #pragma unroll
        for (int i = 0; i < 4; i++) {
            int cid = tid + 256 * i;
            int row = cid >> 3, c16 = cid & 7;
            size_t go = ((size_t)(m0c + rank * 128 + row) * Kstride + k0) * 2 + c16 * 16;
            uint32_t sw = SMEM_SWIZZLE_128B((uint32_t)(row * 128 + c16 * 16));
            CP_ASYNC16(stage + sw,         (const char*)Ahi + go);
            CP_ASYNC16(stage + 16384 + sw, (const char*)Alo + go);
        }
        #pragma unroll
        for (int i = 0; i < 4; i++) {
            int cid = tid + 256 * i;
            int row = cid >> 3, c16 = cid & 7;
            size_t go = ((size_t)(n0 + rank * 128 + row) * Kstride + k0) * 2 + c16 * 16;
            uint32_t sw = SMEM_SWIZZLE_128B((uint32_t)(row * 128 + c16 * 16));
            CP_ASYNC16(stage + 32768 + sw, (const char*)Bhi + go);
            CP_ASYNC16(stage + 49152 + sw, (const char*)Blo + go);
        }
        CP_COMMIT();
    };

    // prologue: stages 0 and 1 in flight
    load_stage(0);
    load_stage(1);

    int phD[NSTAGE] = {0, 0, 0};

    #pragma unroll 1
    for (int s = 0; s < NC; s++) {
        int b = s % NSTAGE;
        if (s == NC - 1) { CP_WAIT0(); } else { CP_WAIT1(); }
        FENCE_PROXY_ASYNC_SHARED_CTA();
        __syncthreads();

        if (wid == 0 && elect_one_pred()) {
            uint32_t readyb = sb + OFF_READY(b);
            if (rank == 0) {
                MBARRIER_ARRIVE(readyb);
                MBARRIER_WAIT_PARITY(readyb, (s / NSTAGE) & 1);
                uint32_t stage = sb + OFF_TILES + (uint32_t)b * STAGE_BYTES;
                uint64_t dAh = MAKE_SMEM_DESC(stage);
                uint64_t dAl = MAKE_SMEM_DESC(stage + 16384);
                uint64_t dBh = MAKE_SMEM_DESC(stage + 32768);
                uint64_t dBl = MAKE_SMEM_DESC(stage + 49152);
                #pragma unroll
                for (int c = 0; c < 3; c++) {
                    uint64_t dA = (c == 2) ? dAl : dAh;
                    uint64_t dB = (c == 1) ? dBl : dBh;
                    #pragma unroll
                    for (int ks = 0; ks < 4; ks++) {
                        bool en = !(s == 0 && c == 0 && ks == 0);
                        mma_f16_ss_cg2(tmem, dA + ks * 2, dB + ks * 2,
                                       IDESC_256x256, en);
                    }
                }
                TCGEN05_COMMIT_MULTICAST_CG2(sb + OFF_DONE(b), 0x3);
            } else {
                MBARRIER_ARRIVE_CLUSTER(readyb, 0);
            }
        }

        // prefetch stage s+2 (buffer was used by stage s-1)
        if (s + 2 < NC) {
            int bp = (s + 2) % NSTAGE;
            if (s >= 1) {
                MBARRIER_WAIT_PARITY(sb + OFF_DONE(bp), phD[bp] & 1);
                phD[bp]++;
            }
            load_stage(s + 2);
        }
    }

    // drain all outstanding done fires
    #pragma unroll
    for (int b = 0; b < NSTAGE; b++) {
        int tf = (NC - b + NSTAGE - 1) / NSTAGE;   // fires for this barrier
        for (int f = phD[b]; f < tf; f++)
            MBARRIER_WAIT_PARITY(sb + OFF_DONE(b), f & 1);
    }
    TCGEN05_FENCE_AFTER();

    if (wid < 4) {
        int row = m0c + rank * 128 + wid * 32 + lid;
        #pragma unroll 1
        for (int nb = 0; nb < 8; nb++) {
            uint32_t r[32];
            TCGEN05_LD_32X32B_X32(r, tmem + nb * 32);
            TCGEN05_WAIT_LD();
            int nc0 = n0 + nb * 32;
            if (EPI == 0) {
                #pragma unroll
                for (int j = 0; j < 8; j++) {
                    float4 o = make_float4(__uint_as_float(r[4 * j + 0]),
                                           __uint_as_float(r[4 * j + 1]),
                                           __uint_as_float(r[4 * j + 2]),
                                           __uint_as_float(r[4 * j + 3]));
                    *reinterpret_cast<float4*>(outF + (size_t)row * N_total + nc0 + 4 * j) = o;
                }
            } else {
                #pragma unroll
                for (int j = 0; j < 4; j++) {
                    union { __nv_bfloat16 b[8]; uint4 u; } uh, ul;
                    #pragma unroll
                    for (int e = 0; e < 8; e++) {
                        float v = __uint_as_float(r[8 * j + e]);
                        if (EPI == 2) v = gelu_tanh(v);
                        split_bf16(v, uh.b[e], ul.b[e]);
                    }
                    size_t o = (size_t)row * N_total + nc0 + 8 * j;
                    *reinterpret_cast<uint4*>(outHi + o) = uh.u;
                    *reinterpret_cast<uint4*>(outLo + o) = ul.u;
                }
            }
        }
        TCGEN05_FENCE_BEFORE();
    }

    __syncthreads();
    if (wid == 0) {
        TCGEN05_RELINQUISH_CG2();
        TCGEN05_DEALLOC_CG2(tmem, 256);
    }
    CLUSTER_SYNC();
#else
    // ---------------- FFMA fallback ----------------------------------------
    int m0 = m0c + (int)rank * 128;
    float* As = reinterpret_cast<float*>(smem);             // [16][132]
    float* Bs = reinterpret_cast<float*>(smem) + 16 * 132;  // [16][68]
    int tx = tid & 15;
    int ty = tid >> 4;

    #pragma unroll 1
    for (int nchunk = 0; nchunk < 4; nchunk++) {
        int nbase = n0 + nchunk * 64;
        float acc[8][4];
        #pragma unroll
        for (int i = 0; i < 8; i++)
            #pragma unroll
            for (int j = 0; j < 4; j++) acc[i][j] = 0.f;

        #pragma unroll 1
        for (int k0 = Koff; k0 < Koff + Klen; k0 += 16) {
            {
                int row = tid >> 1;
                int kseg = (tid & 1) * 8;
                size_t go = (size_t)(m0 + row) * Kstride + k0 + kseg;
                union { uint4 u; __nv_bfloat16 b[8]; } vh, vl;
                vh.u = *reinterpret_cast<const uint4*>(Ahi + go);
                vl.u = *reinterpret_cast<const uint4*>(Alo + go);
                #pragma unroll
                for (int e = 0; e < 8; e++)
                    As[(kseg + e) * 132 + row] =
                        __bfloat162float(vh.b[e]) + __bfloat162float(vl.b[e]);
            }
            {
                int row = tid >> 2;
                int kseg = (tid & 3) * 4;
                size_t go = (size_t)(nbase + row) * Kstride + k0 + kseg;
                union { uint2 u; __nv_bfloat16 b[4]; } vh, vl;
                vh.u = *reinterpret_cast<const uint2*>(Bhi + go);
                vl.u = *reinterpret_cast<const uint2*>(Blo + go);
                #pragma unroll
                for (int e = 0; e < 4; e++)
                    Bs[(kseg + e) * 68 + row] =
                        __bfloat162float(vh.b[e]) + __bfloat162float(vl.b[e]);
            }
            __syncthreads();
            #pragma unroll
            for (int kk = 0; kk < 16; kk++) {
                float a0[8], b0[4];
                float4 a4a = *reinterpret_cast<const float4*>(&As[kk * 132 + ty * 8]);
                float4 a4b = *reinterpret_cast<const float4*>(&As[kk * 132 + ty * 8 + 4]);
                float4 b4  = *reinterpret_cast<const float4*>(&Bs[kk * 68 + tx * 4]);
                a0[0]=a4a.x; a0[1]=a4a.y; a0[2]=a4a.z; a0[3]=a4a.w;
                a0[4]=a4b.x; a0[5]=a4b.y; a0[6]=a4b.z; a0[7]=a4b.w;
                b0[0]=b4.x;  b0[1]=b4.y;  b0[2]=b4.z;  b0[3]=b4.w;
                #pragma unroll
                for (int i = 0; i < 8; i++)
                    #pragma unroll
                    for (int j = 0; j < 4; j++)
                        acc[i][j] = fmaf(a0[i], b0[j], acc[i][j]);
            }
            __syncthreads();
        }

        #pragma unroll
        for (int i = 0; i < 8; i++) {
            int row = m0 + ty * 8 + i;
            int col = nbase + tx * 4;
            if (EPI == 0) {
                float4 o = make_float4(acc[i][0], acc[i][1], acc[i][2], acc[i][3]);
                *reinterpret_cast<float4*>(outF + (size_t)row * N_total + col) = o;
            } else {
                union { __nv_bfloat16 b[4]; uint2 u; } uh, ul;
                #pragma unroll
                for (int j = 0; j < 4; j++) {
                    float v = acc[i][j];
                    if (EPI == 2) v = gelu_tanh(v);
                    split_bf16(v, uh.b[j], ul.b[j]);
                }
                size_t o = (size_t)row * N_total + col;
                *reinterpret_cast<uint2*>(outHi + o) = uh.u;
                *reinterpret_cast<uint2*>(outLo + o) = ul.u;
            }
        }
    }
#endif
}

// ---------------------------------------------------------------------------
// GEMM wrappers (cluster (2,1,1); grid.x counts CTAs = 2 * n-clusters)
// ---------------------------------------------------------------------------
__global__ void __launch_bounds__(256, 1) __cluster_dims__(2, 1, 1)
compose_fused_kernel(const __nv_bfloat16* A1h, const __nv_bfloat16* A1l,
                     const __nv_bfloat16* B1h, const __nv_bfloat16* B1l,
                     __nv_bfloat16* o1h, __nv_bfloat16* o1l,
                     const __nv_bfloat16* A2h, const __nv_bfloat16* A2l,
                     const __nv_bfloat16* B2h, const __nv_bfloat16* B2l,
                     __nv_bfloat16* o2h, __nv_bfloat16* o2l) {
    extern __shared__ __align__(1024) char smem[];
    int cid = blockIdx.x >> 1;
    if (cid < 64) {
        int m0c = (cid >> 2) * 256;    // 16 m-clusters (M=4096)
        int n0  = (cid & 3) * 256;     // 4 n-tiles (N=1024)
        gemm_body_cg2<1>(A1h, A1l, B1h, B1l, KR, 0, KR, DIM_D,
                         nullptr, o1h, o1l, m0c, n0, smem);
    } else {
        cid -= 64;
        int m0c = (cid >> 4) * 256;    // 4 m-clusters (M=1024)
        int n0  = (cid & 15) * 256;    // 16 n-tiles (N=4096)
        gemm_body_cg2<1>(A2h, A2l, B2h, B2l, KR, 0, KR, DIM_F,
                         nullptr, o2h, o2l, m0c, n0, smem);
    }
}

template <int EPI>
__global__ void __launch_bounds__(256, 1) __cluster_dims__(2, 1, 1)
gemm_kernel(const __nv_bfloat16* Ahi, const __nv_bfloat16* Alo,
            const __nv_bfloat16* Bhi, const __nv_bfloat16* Blo,
            int Kstride, int Koff, int Klen, int N_total,
            float* outF, __nv_bfloat16* outHi, __nv_bfloat16* outLo) {
    extern __shared__ __align__(1024) char smem[];
    gemm_body_cg2<EPI>(Ahi, Alo, Bhi, Blo, Kstride, Koff, Klen, N_total,
                       outF, outHi, outLo, blockIdx.y * 256,
                       (blockIdx.x >> 1) * 256, smem);
}

__global__ void __launch_bounds__(256, 1) __cluster_dims__(2, 1, 1)
gemm_splitk_kernel(const __nv_bfloat16* Ahi, const __nv_bfloat16* Alo,
                   const __nv_bfloat16* Bhi, const __nv_bfloat16* Blo,
                   int Kstride, int N_total, float* p0, float* p1) {
    extern __shared__ __align__(1024) char smem[];
    int z = blockIdx.z;
    gemm_body_cg2<0>(Ahi, Alo, Bhi, Blo, Kstride, z * (Kstride / 2), Kstride / 2,
                     N_total, z ? p1 : p0, nullptr, nullptr,
                     blockIdx.y * 256, (blockIdx.x >> 1) * 256, smem);
}

// ---------------------------------------------------------------------------
// Launch
// ---------------------------------------------------------------------------
extern "C" void kernel_launch(void* const* d_in, const int* in_sizes, int n_in,
                              void* d_out, int out_size) {
    const float* x     = (const float*)d_in[0];
    const float* fc1_A = (const float*)d_in[1];
    const float* fc1_B = (const float*)d_in[2];
    const float* fc2_A = (const float*)d_in[3];
    const float* fc2_B = (const float*)d_in[4];
    const float* l1    = (const float*)d_in[5];
    const float* l2    = (const float*)d_in[6];
    float* out = (float*)d_out;

    __nv_bfloat16 *xh, *xl, *Ab1h, *Ab1l, *Bb1th, *Bb1tl, *Ab2h, *Ab2l,
                  *Bb2th, *Bb2tl, *W1th, *W1tl, *W2th, *W2tl, *hh, *hl;
    float *p0, *p1;
    cudaGetSymbolAddress((void**)&xh, g_xh);     cudaGetSymbolAddress((void**)&xl, g_xl);
    cudaGetSymbolAddress((void**)&Ab1h, g_Ab1h); cudaGetSymbolAddress((void**)&Ab1l, g_Ab1l);
    cudaGetSymbolAddress((void**)&Bb1th, g_Bb1th); cudaGetSymbolAddress((void**)&Bb1tl, g_Bb1tl);
    cudaGetSymbolAddress((void**)&Ab2h, g_Ab2h); cudaGetSymbolAddress((void**)&Ab2l, g_Ab2l);
    cudaGetSymbolAddress((void**)&Bb2th, g_Bb2th); cudaGetSymbolAddress((void**)&Bb2tl, g_Bb2tl);
    cudaGetSymbolAddress((void**)&W1th, g_W1th); cudaGetSymbolAddress((void**)&W1tl, g_W1tl);
    cudaGetSymbolAddress((void**)&W2th, g_W2th); cudaGetSymbolAddress((void**)&W2tl, g_W2tl);
    cudaGetSymbolAddress((void**)&hh, g_hh);     cudaGetSymbolAddress((void**)&hl, g_hl);
    cudaGetSymbolAddress((void**)&p0, g_p0);     cudaGetSymbolAddress((void**)&p1, g_p1);

    cudaFuncSetAttribute(compose_fused_kernel, cudaFuncAttributeMaxDynamicSharedMemorySize, GEMM_SMEM);
    cudaFuncSetAttribute(gemm_kernel<2>, cudaFuncAttributeMaxDynamicSharedMemorySize, GEMM_SMEM);
    cudaFuncSetAttribute(gemm_splitk_kernel, cudaFuncAttributeMaxDynamicSharedMemorySize, GEMM_SMEM);

    topk_softmax_kernel<<<2, 32>>>(l1, l2);

    {
        size_t n8;
        n8 = (size_t)BS * DIM_D / 8;
        conv_split_kernel<<<(unsigned)((n8 + 255) / 256), 256>>>(x, xh, xl, (size_t)BS * DIM_D);
        n8 = (size_t)DIM_D * KR / 8;
        gather_A_kernel<<<(unsigned)((n8 + 255) / 256), 256>>>(fc1_A, Ab1h, Ab1l, DIM_D, 0);
        n8 = (size_t)DIM_F * KR / 8;
        gather_A_kernel<<<(unsigned)((n8 + 255) / 256), 256>>>(fc2_A, Ab2h, Ab2l, DIM_F, 1);
        gather_Bt_kernel<<<dim3(DIM_F / 64, TOPK), 256>>>(fc1_B, Bb1th, Bb1tl, DIM_F, 0);
        gather_Bt_kernel<<<dim3(DIM_D / 64, TOPK), 256>>>(fc2_B, Bb2th, Bb2tl, DIM_D, 1);
    }

    // Fused compose: W1t (F x D) and W2t (D x F); 128 clusters = 256 CTAs
    compose_fused_kernel<<<256, 256, GEMM_SMEM>>>(
        Bb1th, Bb1tl, Ab1h, Ab1l, W1th, W1tl,
        Bb2th, Bb2tl, Ab2h, Ab2l, W2th, W2tl);

    // h (BS x F) = gelu( x @ W1t^T )
    gemm_kernel<2><<<dim3(DIM_F / 256 * 2, BS / 256), 256, GEMM_SMEM>>>(
        xh, xl, W1th, W1tl, DIM_D, 0, DIM_D, DIM_F, nullptr, hh, hl);

    // out (BS x D) = h @ W2t^T  — split-K x2 + add
    gemm_splitk_kernel<<<dim3(DIM_D / 256 * 2, BS / 256, 2), 256, GEMM_SMEM>>>(
        hh, hl, W2th, W2tl, DIM_F, DIM_D, p0, p1);
    add_kernel<<<(BS * DIM_D / 4 + 255) / 256, 256>>>(p0, p1, out, (size_t)BS * DIM_D / 4);
}